// round 4
// baseline (speedup 1.0000x reference)
#include <cuda_runtime.h>
#include <math.h>

#define B_    8
#define TS    2
#define SEQ   720
#define ENC   862
#define MARKD 4
#define NTOK  866
#define D     256
#define NH    8
#define EH    32
#define DFF   512
#define DB    720
#define LAYERS 2
#define EPS   1e-5f
#define MROWS (B_*NTOK)   // 6928

// ---------------- scratch (device globals; no allocation) ----------------
__device__ float g_xin [(size_t)MROWS*SEQ];
__device__ float g_mean[B_*ENC];
__device__ float g_std [B_*ENC];
__device__ float g_h   [(size_t)MROWS*D];
__device__ float g_qkv [(size_t)3*MROWS*D];
__device__ float g_att [(size_t)MROWS*D];
__device__ float g_xatt[(size_t)MROWS*D];
__device__ float g_xln [(size_t)MROWS*D];
__device__ float g_y1  [(size_t)MROWS*DFF];
__device__ float g_y   [(size_t)MROWS*D];
__device__ float g_xs  [(size_t)MROWS*D];
__device__ float g_hh  [(size_t)MROWS*D];
__device__ float g_cat [(size_t)MROWS*2*D];
__device__ float g_o56 [(size_t)2*MROWS*DB];
__device__ float g_out [(size_t)MROWS*DB];
__device__ float g_scores[(size_t)B_*NH*NTOK*NTOK];   // 192 MB

// ---------------- f32x2 helpers (sm_103a packed fp32) ----------------
__device__ __forceinline__ unsigned long long ffma2(unsigned long long a,
                                                    unsigned long long b,
                                                    unsigned long long c){
    unsigned long long d;
    asm("fma.rn.f32x2 %0, %1, %2, %3;" : "=l"(d) : "l"(a), "l"(b), "l"(c));
    return d;
}
__device__ __forceinline__ unsigned long long packdup(float x){
    unsigned long long d;
    asm("mov.b64 %0, {%1, %1};" : "=l"(d) : "f"(x));
    return d;
}
__device__ __forceinline__ float2 unpack2(unsigned long long v){
    float lo, hi;
    asm("mov.b64 {%0, %1}, %2;" : "=f"(lo), "=f"(hi) : "l"(v));
    return make_float2(lo, hi);
}

// ---------------- reductions ----------------
__device__ __forceinline__ float blockReduce(float v, bool domax){
    __shared__ float sh[33];
    int lane = threadIdx.x & 31, wid = threadIdx.x >> 5;
    __syncthreads();
    #pragma unroll
    for (int o = 16; o; o >>= 1){
        float ov = __shfl_down_sync(0xffffffffu, v, o);
        v = domax ? fmaxf(v, ov) : (v + ov);
    }
    if (lane == 0) sh[wid] = v;
    __syncthreads();
    if (wid == 0){
        int nw = blockDim.x >> 5;
        v = (lane < nw) ? sh[lane] : (domax ? -1e30f : 0.f);
        #pragma unroll
        for (int o = 16; o; o >>= 1){
            float ov = __shfl_down_sync(0xffffffffu, v, o);
            v = domax ? fmaxf(v, ov) : (v + ov);
        }
        if (lane == 0) sh[32] = v;
    }
    __syncthreads();
    return sh[32];
}

// ---------------- input standardization stats ----------------
__global__ void stats_kernel(const float* __restrict__ mbx, int t){
    int b = blockIdx.y;
    int n = blockIdx.x * blockDim.x + threadIdx.x;
    if (n >= ENC) return;
    const float* base = mbx + ((size_t)(b*TS + t)*SEQ)*ENC + n;
    float s = 0.f, ss = 0.f;
    for (int i = 0; i < SEQ; i++){
        float v = base[(size_t)i*ENC];
        s += v; ss += v*v;
    }
    float m = s * (1.f/SEQ);
    float var = ss * (1.f/SEQ) - m*m;
    g_mean[b*ENC + n] = m;
    g_std [b*ENC + n] = sqrtf(var + EPS);
}

// ---------------- build xin [B, NTOK, SEQ] ----------------
__global__ void xin_kernel(const float* __restrict__ mbx,
                           const float* __restrict__ mbxm, int t){
    size_t total = (size_t)B_*NTOK*SEQ;
    size_t idx = (size_t)blockIdx.x*blockDim.x + threadIdx.x;
    if (idx >= total) return;
    int s = (int)(idx % SEQ);
    size_t r = idx / SEQ;
    int n = (int)(r % NTOK);
    int b = (int)(r / NTOK);
    float v;
    if (n < ENC){
        v = mbx[((size_t)(b*TS + t)*SEQ + s)*ENC + n];
        v = (v - g_mean[b*ENC + n]) / g_std[b*ENC + n];
    } else {
        v = mbxm[((size_t)(b*TS + t)*SEQ + s)*MARKD + (n - ENC)];
    }
    g_xin[idx] = v;
}

// ---------------- GEMM: C = A @ W^T + bias (FFMA2, double-buffered) ------
struct GemmArgs {
    const float* A[3];
    const float* W[3];
    const float* Bv[3];
    float*       C[3];
};

template<int TM, int TN, int ACT>
__global__ __launch_bounds__(256)
void gemm2_kernel(GemmArgs p, int M, int N, int K,
                  int tilesM, int tilesN, int nTiles){
    constexpr int AV  = TM/64;      // float4 loads per thread for A tile
    constexpr int BV  = TN/64;
    constexpr int TMR = TM/16;      // rows per thread
    constexpr int TNR = TN/16;      // cols per thread

    __shared__ __align__(16) float              As[2][16][TM];
    __shared__ __align__(16) unsigned long long Bs[2][16][TN]; // (b,b) dup

    const int tid   = threadIdx.x;
    const int ldRow = tid >> 2;        // 0..63
    const int ldCol = (tid & 3) * 4;   // 0,4,8,12
    const int tr = tid >> 4, tc = tid & 15;
    const int tpz = tilesM * tilesN;

    for (int t = blockIdx.x; t < nTiles; t += gridDim.x){
        const int z  = t / tpz;
        const int r  = t - z*tpz;
        const int bm = (r / tilesN) * TM;
        const int bn = (r % tilesN) * TN;
        const float* __restrict__ A    = p.A[z];
        const float* __restrict__ W    = p.W[z];
        const float* __restrict__ bias = p.Bv[z];
        float*       __restrict__ C    = p.C[z];

        unsigned long long acc[TMR/2][TNR];
        #pragma unroll
        for (int i = 0; i < TMR/2; i++)
            #pragma unroll
            for (int j = 0; j < TNR; j++) acc[i][j] = 0ull;

        float4 Areg[AV], Breg[BV];
        // prologue: load k-tile 0
        #pragma unroll
        for (int v = 0; v < AV; v++){
            int gm = bm + ldRow + 64*v;
            Areg[v] = (gm < M) ? *(const float4*)(A + (size_t)gm*K + ldCol)
                               : make_float4(0.f,0.f,0.f,0.f);
        }
        #pragma unroll
        for (int v = 0; v < BV; v++){
            int gn = bn + ldRow + 64*v;
            Breg[v] = (gn < N) ? *(const float4*)(W + (size_t)gn*K + ldCol)
                               : make_float4(0.f,0.f,0.f,0.f);
        }
        #pragma unroll
        for (int v = 0; v < AV; v++){
            int row = ldRow + 64*v;
            As[0][ldCol+0][row] = Areg[v].x; As[0][ldCol+1][row] = Areg[v].y;
            As[0][ldCol+2][row] = Areg[v].z; As[0][ldCol+3][row] = Areg[v].w;
        }
        #pragma unroll
        for (int v = 0; v < BV; v++){
            int row = ldRow + 64*v;
            Bs[0][ldCol+0][row] = packdup(Breg[v].x);
            Bs[0][ldCol+1][row] = packdup(Breg[v].y);
            Bs[0][ldCol+2][row] = packdup(Breg[v].z);
            Bs[0][ldCol+3][row] = packdup(Breg[v].w);
        }
        __syncthreads();

        const int KT = K >> 4;
        int buf = 0;
        for (int kt = 0; kt < KT; kt++){
            if (kt + 1 < KT){
                const int k0 = (kt+1) << 4;
                #pragma unroll
                for (int v = 0; v < AV; v++){
                    int gm = bm + ldRow + 64*v;
                    Areg[v] = (gm < M) ? *(const float4*)(A + (size_t)gm*K + k0 + ldCol)
                                       : make_float4(0.f,0.f,0.f,0.f);
                }
                #pragma unroll
                for (int v = 0; v < BV; v++){
                    int gn = bn + ldRow + 64*v;
                    Breg[v] = (gn < N) ? *(const float4*)(W + (size_t)gn*K + k0 + ldCol)
                                       : make_float4(0.f,0.f,0.f,0.f);
                }
            }
            #pragma unroll
            for (int kk = 0; kk < 16; kk++){
                const ulonglong2* pa = reinterpret_cast<const ulonglong2*>(&As[buf][kk][tr*TMR]);
                const ulonglong2* pb = reinterpret_cast<const ulonglong2*>(&Bs[buf][kk][tc*TNR]);
                unsigned long long ar[TMR/2], br[TNR];
                #pragma unroll
                for (int v = 0; v < TMR/4; v++){
                    ulonglong2 q = pa[v];
                    ar[2*v] = q.x; ar[2*v+1] = q.y;
                }
                #pragma unroll
                for (int v = 0; v < TNR/2; v++){
                    ulonglong2 q = pb[v];
                    br[2*v] = q.x; br[2*v+1] = q.y;
                }
                #pragma unroll
                for (int i = 0; i < TMR/2; i++)
                    #pragma unroll
                    for (int j = 0; j < TNR; j++)
                        acc[i][j] = ffma2(ar[i], br[j], acc[i][j]);
            }
            if (kt + 1 < KT){
                int nb = buf ^ 1;
                #pragma unroll
                for (int v = 0; v < AV; v++){
                    int row = ldRow + 64*v;
                    As[nb][ldCol+0][row] = Areg[v].x; As[nb][ldCol+1][row] = Areg[v].y;
                    As[nb][ldCol+2][row] = Areg[v].z; As[nb][ldCol+3][row] = Areg[v].w;
                }
                #pragma unroll
                for (int v = 0; v < BV; v++){
                    int row = ldRow + 64*v;
                    Bs[nb][ldCol+0][row] = packdup(Breg[v].x);
                    Bs[nb][ldCol+1][row] = packdup(Breg[v].y);
                    Bs[nb][ldCol+2][row] = packdup(Breg[v].z);
                    Bs[nb][ldCol+3][row] = packdup(Breg[v].w);
                }
                __syncthreads();
                buf ^= 1;
            }
        }

        #pragma unroll
        for (int i = 0; i < TMR/2; i++){
            int gm0 = bm + tr*TMR + 2*i;
            #pragma unroll
            for (int j = 0; j < TNR; j++){
                int col = bn + tc*TNR + j;
                if (col >= N) continue;
                float2 v = unpack2(acc[i][j]);
                float bs = bias[col];
                float c0 = v.x + bs, c1 = v.y + bs;
                if (ACT == 1){
                    c0 = 0.5f*c0*(1.f + erff(c0*0.70710678118654752f));
                    c1 = 0.5f*c1*(1.f + erff(c1*0.70710678118654752f));
                }
                if (gm0     < M) C[(size_t)gm0    *N + col] = c0;
                if (gm0 + 1 < M) C[(size_t)(gm0+1)*N + col] = c1;
            }
        }
        __syncthreads();
    }
}

// ---------------- attention: scores = scale * Q K^T (f32x2 k-packing) ----
__global__ __launch_bounds__(256) void scores_kernel(){
    const int bh = blockIdx.z;
    const int b = bh >> 3, h = bh & 7;
    const int i0 = blockIdx.y * 64, j0 = blockIdx.x * 64;
    __shared__ __align__(16) float Qs[64][36];
    __shared__ __align__(16) float Ks[64][36];
    const float* q = g_qkv + ((size_t)b*NTOK)*D + h*EH;
    const float* k = g_qkv + (size_t)MROWS*D + ((size_t)b*NTOK)*D + h*EH;

    for (int idx = threadIdx.x; idx < 64*32; idx += 256){
        int r = idx >> 5, e = idx & 31;
        int gi = i0 + r, gj = j0 + r;
        Qs[r][e] = (gi < NTOK) ? q[(size_t)gi*D + e] : 0.f;
        Ks[r][e] = (gj < NTOK) ? k[(size_t)gj*D + e] : 0.f;
    }
    __syncthreads();

    const int tr = threadIdx.x & 15, tc = threadIdx.x >> 4;
    unsigned long long acc[4][4];
    #pragma unroll
    for (int i = 0; i < 4; i++)
        #pragma unroll
        for (int j = 0; j < 4; j++) acc[i][j] = 0ull;

    #pragma unroll
    for (int ee = 0; ee < 32; ee += 4){
        ulonglong2 qa[4], kb[4];
        #pragma unroll
        for (int i = 0; i < 4; i++)
            qa[i] = *reinterpret_cast<const ulonglong2*>(&Qs[tr + 16*i][ee]);
        #pragma unroll
        for (int j = 0; j < 4; j++)
            kb[j] = *reinterpret_cast<const ulonglong2*>(&Ks[tc*4 + j][ee]);
        #pragma unroll
        for (int i = 0; i < 4; i++)
            #pragma unroll
            for (int j = 0; j < 4; j++){
                acc[i][j] = ffma2(qa[i].x, kb[j].x, acc[i][j]);
                acc[i][j] = ffma2(qa[i].y, kb[j].y, acc[i][j]);
            }
    }

    float* S = g_scores + (size_t)bh*NTOK*NTOK;
    const float scale = 0.17677669529663688f;  // 1/sqrt(32)
    #pragma unroll
    for (int i = 0; i < 4; i++){
        int gi = i0 + tr + 16*i;
        if (gi >= NTOK) continue;
        #pragma unroll
        for (int j = 0; j < 4; j++){
            int gj = j0 + tc*4 + j;
            if (gj < NTOK){
                float2 v = unpack2(acc[i][j]);
                S[(size_t)gi*NTOK + gj] = (v.x + v.y)*scale;
            }
        }
    }
}

// ---------------- softmax over last dim (rows of 866) ----------------
__global__ __launch_bounds__(128) void softmax_kernel(){
    size_t row = blockIdx.x;
    float* p = g_scores + row*(size_t)NTOK;
    float v[7];
    float mx = -1e30f;
    #pragma unroll
    for (int i = 0; i < 7; i++){
        int j = threadIdx.x + i*128;
        v[i] = (j < NTOK) ? p[j] : -1e30f;
        mx = fmaxf(mx, v[i]);
    }
    mx = blockReduce(mx, true);
    float sum = 0.f;
    #pragma unroll
    for (int i = 0; i < 7; i++){
        v[i] = expf(v[i] - mx);
        sum += v[i];
    }
    sum = blockReduce(sum, false);
    float inv = 1.f / sum;
    #pragma unroll
    for (int i = 0; i < 7; i++){
        int j = threadIdx.x + i*128;
        if (j < NTOK) p[j] = v[i]*inv;
    }
}

// ---------------- att = P @ V (f32x2 j-packing) ----------------
__global__ __launch_bounds__(256) void av_kernel(){
    const int bh = blockIdx.y;
    const int b = bh >> 3, h = bh & 7;
    const int i0 = blockIdx.x * 64;
    __shared__ __align__(16) float Ps [64][68];
    __shared__ __align__(16) float VsT[32][68];
    const float* S = g_scores + (size_t)bh*NTOK*NTOK;
    const float* v = g_qkv + 2*(size_t)MROWS*D + ((size_t)b*NTOK)*D + h*EH;
    const int tr = threadIdx.x & 15, tc = threadIdx.x >> 4;

    unsigned long long acc[4][2];
    #pragma unroll
    for (int i = 0; i < 4; i++){ acc[i][0] = 0ull; acc[i][1] = 0ull; }

    for (int j0 = 0; j0 < NTOK; j0 += 64){
        __syncthreads();
        for (int idx = threadIdx.x; idx < 64*64; idx += 256){
            int li = idx >> 6, lj = idx & 63;
            int gi = i0 + li, gj = j0 + lj;
            Ps[li][lj] = (gi < NTOK && gj < NTOK) ? S[(size_t)gi*NTOK + gj] : 0.f;
        }
        for (int idx = threadIdx.x; idx < 64*32; idx += 256){
            int lj = idx >> 5, e = idx & 31;
            int gj = j0 + lj;
            VsT[e][lj] = (gj < NTOK) ? v[(size_t)gj*D + e] : 0.f;
        }
        __syncthreads();
        #pragma unroll
        for (int jj = 0; jj < 64; jj += 4){
            ulonglong2 pa[4], vb[2];
            #pragma unroll
            for (int i = 0; i < 4; i++)
                pa[i] = *reinterpret_cast<const ulonglong2*>(&Ps[tr + 16*i][jj]);
            #pragma unroll
            for (int c = 0; c < 2; c++)
                vb[c] = *reinterpret_cast<const ulonglong2*>(&VsT[tc*2 + c][jj]);
            #pragma unroll
            for (int i = 0; i < 4; i++)
                #pragma unroll
                for (int c = 0; c < 2; c++){
                    acc[i][c] = ffma2(pa[i].x, vb[c].x, acc[i][c]);
                    acc[i][c] = ffma2(pa[i].y, vb[c].y, acc[i][c]);
                }
        }
    }
    #pragma unroll
    for (int i = 0; i < 4; i++){
        int gi = i0 + tr + 16*i;
        if (gi >= NTOK) continue;
        #pragma unroll
        for (int c = 0; c < 2; c++){
            float2 u = unpack2(acc[i][c]);
            g_att[((size_t)b*NTOK + gi)*D + h*EH + tc*2 + c] = u.x + u.y;
        }
    }
}

// ---------------- LayerNorm(x [- sub]) over D=256 ----------------
__global__ __launch_bounds__(256) void ln_kernel(const float* __restrict__ X,
                                                 const float* __restrict__ Sub,
                                                 const float* __restrict__ g,
                                                 const float* __restrict__ beta,
                                                 float* __restrict__ Out){
    int row = blockIdx.x, d = threadIdx.x;
    size_t i = (size_t)row*D + d;
    float v = X[i] - (Sub ? Sub[i] : 0.f);
    float mean = blockReduce(v, false) * (1.f/D);
    float dv = v - mean;
    float var = blockReduce(dv*dv, false) * (1.f/D);
    Out[i] = dv * rsqrtf(var + EPS) * g[d] + beta[d];
}

// ---------------- elementwise fusion kernels ----------------
__global__ void sub_kernel(const float* __restrict__ a, const float* __restrict__ b,
                           float* __restrict__ c, size_t n){
    size_t i = (size_t)blockIdx.x*blockDim.x + threadIdx.x;
    if (i < n) c[i] = a[i] - b[i];
}

__global__ void glu_kernel(const float* __restrict__ a, const float* __restrict__ b,
                           float* __restrict__ c, size_t n){
    size_t i = (size_t)blockIdx.x*blockDim.x + threadIdx.x;
    if (i < n) c[i] = (1.f/(1.f + expf(-a[i]))) * b[i];
}

__global__ void cat_kernel(const float* __restrict__ xatt, const float* __restrict__ y){
    size_t n = (size_t)MROWS*2*D;
    size_t i = (size_t)blockIdx.x*blockDim.x + threadIdx.x;
    if (i >= n) return;
    int c = (int)(i % (2*D));
    size_t r = i / (2*D);
    g_cat[i] = (c < D) ? xatt[r*D + c] : y[r*D + c - D];
}

__global__ void outcomb_kernel(int l){
    size_t n = (size_t)MROWS*DB;
    size_t i = (size_t)blockIdx.x*blockDim.x + threadIdx.x;
    if (i >= n) return;
    float a = g_o56[i], b = g_o56[n + i];
    float v = (1.f/(1.f + expf(-a))) * b;
    g_out[i] = l ? (v - g_out[i]) : v;
}

// ---------------- final: de-standardize, transpose, 2-scale mean ----------
__global__ void final_kernel(float* __restrict__ out, int t){
    size_t total = (size_t)B_*DB*ENC;
    size_t idx = (size_t)blockIdx.x*blockDim.x + threadIdx.x;
    if (idx >= total) return;
    int n = (int)(idx % ENC);
    size_t r = idx / ENC;
    int p = (int)(r % DB);
    int b = (int)(r / DB);
    float v = g_out[((size_t)b*NTOK + n)*DB + p] * g_std[b*ENC + n] + g_mean[b*ENC + n];
    v *= 0.5f;
    if (t == 0) out[idx] = v; else out[idx] += v;
}

// ---------------- host ----------------
static inline GemmArgs ga1(const float* A, const float* W, const float* b, float* C){
    GemmArgs g = {};
    g.A[0] = A; g.W[0] = W; g.Bv[0] = b; g.C[0] = C;
    return g;
}
static inline int gsz(int nt){ return nt < 592 ? nt : 592; }

extern "C" void kernel_launch(void* const* d_in, const int* in_sizes, int n_in,
                              void* d_out, int out_size){
    const float* mbx  = (const float*)d_in[0];
    const float* mbxm = (const float*)d_in[1];
    const float* embW = (const float*)d_in[4];
    const float* embB = (const float*)d_in[5];
    const float* Wq = (const float*)d_in[6];
    const float* Wk = (const float*)d_in[7];
    const float* Wv = (const float*)d_in[8];
    const float* Wo = (const float*)d_in[9];
    const float* W3 = (const float*)d_in[10];
    const float* W4 = (const float*)d_in[11];
    const float* bq = (const float*)d_in[12];
    const float* bk = (const float*)d_in[13];
    const float* bv = (const float*)d_in[14];
    const float* bo = (const float*)d_in[15];
    const float* b3 = (const float*)d_in[16];
    const float* b4 = (const float*)d_in[17];
    const float* W1 = (const float*)d_in[18];
    const float* b1 = (const float*)d_in[19];
    const float* W2 = (const float*)d_in[20];
    const float* b2 = (const float*)d_in[21];
    const float* W5 = (const float*)d_in[22];
    const float* b5 = (const float*)d_in[23];
    const float* W6 = (const float*)d_in[24];
    const float* b6 = (const float*)d_in[25];
    const float* ln1g = (const float*)d_in[26];
    const float* ln1b = (const float*)d_in[27];
    const float* ln2g = (const float*)d_in[28];
    const float* ln2b = (const float*)d_in[29];
    float* out = (float*)d_out;

    float *xin, *h, *qkv, *att, *xatt, *xln, *y1, *y, *xs, *hh, *cat, *o56;
    cudaGetSymbolAddress((void**)&xin,  g_xin);
    cudaGetSymbolAddress((void**)&h,    g_h);
    cudaGetSymbolAddress((void**)&qkv,  g_qkv);
    cudaGetSymbolAddress((void**)&att,  g_att);
    cudaGetSymbolAddress((void**)&xatt, g_xatt);
    cudaGetSymbolAddress((void**)&xln,  g_xln);
    cudaGetSymbolAddress((void**)&y1,   g_y1);
    cudaGetSymbolAddress((void**)&y,    g_y);
    cudaGetSymbolAddress((void**)&xs,   g_xs);
    cudaGetSymbolAddress((void**)&hh,   g_hh);
    cudaGetSymbolAddress((void**)&cat,  g_cat);
    cudaGetSymbolAddress((void**)&o56,  g_o56);

    const size_t MD = (size_t)MROWS*D;
    const int tm128 = 55;   // ceil(6928/128)
    const int tm64  = 109;  // ceil(6928/64)

    for (int t = 0; t < TS; t++){
        stats_kernel<<<dim3((ENC + 255)/256, B_), 256>>>(mbx, t);
        {
            size_t n = (size_t)B_*NTOK*SEQ;
            xin_kernel<<<(unsigned)((n + 255)/256), 256>>>(mbx, mbxm, t);
        }
        // embed: M=6928, N=256, K=720
        gemm2_kernel<64,64,0><<<gsz(tm64*4), 256>>>(
            ga1(xin, embW, embB, h), MROWS, D, SEQ, tm64, 4, tm64*4);

        for (int l = 0; l < LAYERS; l++){
            // Q, K, V in one launch
            GemmArgs q3 = {};
            q3.A[0] = h; q3.A[1] = h; q3.A[2] = h;
            q3.W[0] = Wq + (size_t)l*D*D; q3.W[1] = Wk + (size_t)l*D*D; q3.W[2] = Wv + (size_t)l*D*D;
            q3.Bv[0] = bq + l*D; q3.Bv[1] = bk + l*D; q3.Bv[2] = bv + l*D;
            q3.C[0] = qkv; q3.C[1] = qkv + MD; q3.C[2] = qkv + 2*MD;
            gemm2_kernel<128,64,0><<<gsz(tm128*4*3), 256>>>(q3, MROWS, D, D,
                                                            tm128, 4, tm128*4*3);

            scores_kernel<<<dim3(14, 14, B_*NH), 256>>>();
            softmax_kernel<<<B_*NH*NTOK, 128>>>();
            av_kernel<<<dim3(14, B_*NH), 256>>>();

            gemm2_kernel<64,64,0><<<gsz(tm64*4), 256>>>(
                ga1(att, Wo + (size_t)l*D*D, bo + l*D, xatt), MROWS, D, D,
                tm64, 4, tm64*4);

            ln_kernel<<<MROWS, 256>>>(h, xatt, ln1g + l*D, ln1b + l*D, xln);

            gemm2_kernel<128,64,1><<<gsz(tm128*8), 256>>>(
                ga1(xln, W1 + (size_t)l*DFF*D, b1 + l*DFF, y1), MROWS, DFF, D,
                tm128, 8, tm128*8);
            gemm2_kernel<64,64,0><<<gsz(tm64*4), 256>>>(
                ga1(y1, W2 + (size_t)l*D*DFF, b2 + l*D, y), MROWS, D, DFF,
                tm64, 4, tm64*4);

            sub_kernel<<<(unsigned)((MD + 255)/256), 256>>>(xln, y, xs, MD);

            GemmArgs g34 = {};
            g34.A[0] = xs; g34.A[1] = xs;
            g34.W[0] = W3 + (size_t)l*D*D; g34.W[1] = W4 + (size_t)l*D*D;
            g34.Bv[0] = b3 + l*D; g34.Bv[1] = b4 + l*D;
            g34.C[0] = qkv; g34.C[1] = qkv + MD;   // reuse q/k slots
            gemm2_kernel<128,64,0><<<gsz(tm128*4*2), 256>>>(g34, MROWS, D, D,
                                                            tm128, 4, tm128*4*2);

            glu_kernel<<<(unsigned)((MD + 255)/256), 256>>>(qkv, qkv + MD, hh, MD);
            cat_kernel<<<(unsigned)(((size_t)MROWS*2*D + 255)/256), 256>>>(xatt, y);

            GemmArgs g56 = {};
            g56.A[0] = cat; g56.A[1] = cat;
            g56.W[0] = W5 + (size_t)l*DB*2*D; g56.W[1] = W6 + (size_t)l*DB*2*D;
            g56.Bv[0] = b5 + l*DB; g56.Bv[1] = b6 + l*DB;
            g56.C[0] = o56; g56.C[1] = o56 + (size_t)MROWS*DB;
            gemm2_kernel<128,64,0><<<gsz(tm128*12*2), 256>>>(g56, MROWS, DB, 2*D,
                                                             tm128, 12, tm128*12*2);

            outcomb_kernel<<<(unsigned)(((size_t)MROWS*DB + 255)/256), 256>>>(l);

            ln_kernel<<<MROWS, 256>>>(hh, (const float*)nullptr, ln2g + l*D, ln2b + l*D, h);
        }

        final_kernel<<<(unsigned)(((size_t)B_*DB*ENC + 255)/256), 256>>>(out, t);
    }
}

// round 5
// speedup vs baseline: 1.6715x; 1.6715x over previous
#include <cuda_runtime.h>
#include <cuda_bf16.h>
#include <math.h>

#define B_    8
#define TS    2
#define SEQ   720
#define ENC   862
#define MARKD 4
#define NTOK  866
#define D     256
#define NH    8
#define EH    32
#define DFF   512
#define DB    720
#define LAYERS 2
#define EPS   1e-5f
#define MROWS (B_*NTOK)   // 6928
#define SLD   896         // padded score row stride

// ---------------- scratch (device globals; no allocation) ----------------
__device__ float g_xin [(size_t)MROWS*SEQ];
__device__ float g_mean[B_*ENC];
__device__ float g_std [B_*ENC];
__device__ float g_h   [(size_t)MROWS*D];
__device__ float g_qkv [(size_t)3*MROWS*D];
__device__ float g_att [(size_t)MROWS*D];
__device__ float g_xatt[(size_t)MROWS*D];
__device__ float g_xln [(size_t)MROWS*D];
__device__ float g_y1  [(size_t)MROWS*DFF];
__device__ float g_y   [(size_t)MROWS*D];
__device__ float g_xs  [(size_t)MROWS*D];
__device__ float g_hh  [(size_t)MROWS*D];
__device__ float g_cat [(size_t)MROWS*2*D];
__device__ float g_o56 [(size_t)2*MROWS*DB];
__device__ float g_out [(size_t)MROWS*DB];
__device__ float g_scores[(size_t)B_*NH*NTOK*SLD];   // padded rows

// ---------------- mma / ldmatrix helpers ----------------
__device__ __forceinline__ void mma_bf16(float c[4], const unsigned a[4], const unsigned b[2]){
    asm volatile("mma.sync.aligned.m16n8k16.row.col.f32.bf16.bf16.f32 "
                 "{%0,%1,%2,%3}, {%4,%5,%6,%7}, {%8,%9}, {%0,%1,%2,%3};\n"
                 : "+f"(c[0]), "+f"(c[1]), "+f"(c[2]), "+f"(c[3])
                 : "r"(a[0]), "r"(a[1]), "r"(a[2]), "r"(a[3]),
                   "r"(b[0]), "r"(b[1]));
}
__device__ __forceinline__ void ldsm_x4(unsigned r[4], unsigned addr){
    asm volatile("ldmatrix.sync.aligned.m8n8.x4.shared.b16 {%0,%1,%2,%3}, [%4];\n"
                 : "=r"(r[0]), "=r"(r[1]), "=r"(r[2]), "=r"(r[3]) : "r"(addr));
}
__device__ __forceinline__ void ldsm_x4t(unsigned r[4], unsigned addr){
    asm volatile("ldmatrix.sync.aligned.m8n8.x4.trans.shared.b16 {%0,%1,%2,%3}, [%4];\n"
                 : "=r"(r[0]), "=r"(r[1]), "=r"(r[2]), "=r"(r[3]) : "r"(addr));
}
// split 4 fp32 into hi/lo bf16 and store (contiguous, 4-elt aligned)
__device__ __forceinline__ void split4(float4 f, __nv_bfloat16* ph, __nv_bfloat16* pl){
    __nv_bfloat16 h0 = __float2bfloat16(f.x), h1 = __float2bfloat16(f.y);
    __nv_bfloat16 h2 = __float2bfloat16(f.z), h3 = __float2bfloat16(f.w);
    *(__nv_bfloat162*)(ph)     = __halves2bfloat162(h0, h1);
    *(__nv_bfloat162*)(ph + 2) = __halves2bfloat162(h2, h3);
    *(__nv_bfloat162*)(pl)     = __halves2bfloat162(
        __float2bfloat16(f.x - __bfloat162float(h0)),
        __float2bfloat16(f.y - __bfloat162float(h1)));
    *(__nv_bfloat162*)(pl + 2) = __halves2bfloat162(
        __float2bfloat16(f.z - __bfloat162float(h2)),
        __float2bfloat16(f.w - __bfloat162float(h3)));
}
__device__ __forceinline__ float gelu_f(float x){
    return 0.5f*x*(1.f + erff(x*0.70710678118654752f));
}

// ---------------- reductions ----------------
__device__ __forceinline__ float blockReduce(float v, bool domax){
    __shared__ float sh[33];
    int lane = threadIdx.x & 31, wid = threadIdx.x >> 5;
    __syncthreads();
    #pragma unroll
    for (int o = 16; o; o >>= 1){
        float ov = __shfl_down_sync(0xffffffffu, v, o);
        v = domax ? fmaxf(v, ov) : (v + ov);
    }
    if (lane == 0) sh[wid] = v;
    __syncthreads();
    if (wid == 0){
        int nw = blockDim.x >> 5;
        v = (lane < nw) ? sh[lane] : (domax ? -1e30f : 0.f);
        #pragma unroll
        for (int o = 16; o; o >>= 1){
            float ov = __shfl_down_sync(0xffffffffu, v, o);
            v = domax ? fmaxf(v, ov) : (v + ov);
        }
        if (lane == 0) sh[32] = v;
    }
    __syncthreads();
    return sh[32];
}

// ---------------- input standardization stats ----------------
__global__ void stats_kernel(const float* __restrict__ mbx, int t){
    int b = blockIdx.y;
    int n = blockIdx.x * blockDim.x + threadIdx.x;
    if (n >= ENC) return;
    const float* base = mbx + ((size_t)(b*TS + t)*SEQ)*ENC + n;
    float s = 0.f, ss = 0.f;
    for (int i = 0; i < SEQ; i++){
        float v = base[(size_t)i*ENC];
        s += v; ss += v*v;
    }
    float m = s * (1.f/SEQ);
    float var = ss * (1.f/SEQ) - m*m;
    g_mean[b*ENC + n] = m;
    g_std [b*ENC + n] = sqrtf(var + EPS);
}

// ---------------- build xin [B, NTOK, SEQ] ----------------
__global__ void xin_kernel(const float* __restrict__ mbx,
                           const float* __restrict__ mbxm, int t){
    size_t total = (size_t)B_*NTOK*SEQ;
    size_t idx = (size_t)blockIdx.x*blockDim.x + threadIdx.x;
    if (idx >= total) return;
    int s = (int)(idx % SEQ);
    size_t r = idx / SEQ;
    int n = (int)(r % NTOK);
    int b = (int)(r / NTOK);
    float v;
    if (n < ENC){
        v = mbx[((size_t)(b*TS + t)*SEQ + s)*ENC + n];
        v = (v - g_mean[b*ENC + n]) / g_std[b*ENC + n];
    } else {
        v = mbxm[((size_t)(b*TS + t)*SEQ + s)*MARKD + (n - ENC)];
    }
    g_xin[idx] = v;
}

// =============== MMA GEMM engine: C = A @ W^T + bias =====================
// BM=128, BN=64, BK=32, 256 threads = 8 warps (4m x 2n), warp tile 32x32.
struct GemmArgs {
    const float* A[3];
    const float* W[3];
    const float* Bv[3];
    float*       C[3];
};

template<int ACT>
__global__ __launch_bounds__(256)
void mma_gemm(GemmArgs p, int M, int N, int K,
              int tilesM, int tilesN, int nTiles){
    __shared__ __align__(16) __nv_bfloat16 Ah[128][40], Al[128][40];
    __shared__ __align__(16) __nv_bfloat16 Bh[64][40],  Bl[64][40];

    const int tid = threadIdx.x;
    const int lane = tid & 31, w = tid >> 5;
    const int wm = (w >> 1)*32, wn = (w & 1)*32;
    const int t4 = lane >> 3, lr = lane & 7;
    const unsigned aHiB = (unsigned)__cvta_generic_to_shared(&Ah[0][0]);
    const unsigned aLoB = (unsigned)__cvta_generic_to_shared(&Al[0][0]);
    const unsigned bHiB = (unsigned)__cvta_generic_to_shared(&Bh[0][0]);
    const unsigned bLoB = (unsigned)__cvta_generic_to_shared(&Bl[0][0]);
    const int tpz = tilesM * tilesN;
    const int aRow = tid >> 1, aK = (tid & 1)*16;
    const int bRow = tid >> 2, bK = (tid & 3)*8;

    for (int t = blockIdx.x; t < nTiles; t += gridDim.x){
        const int z  = t / tpz;
        const int rr = t - z*tpz;
        const int bm = (rr / tilesN)*128, bn = (rr % tilesN)*64;
        const float* __restrict__ A    = p.A[z];
        const float* __restrict__ W    = p.W[z];
        const float* __restrict__ bias = p.Bv[z];
        float*       __restrict__ C    = p.C[z];

        float acc[2][4][4];
        #pragma unroll
        for (int i = 0; i < 2; i++)
            #pragma unroll
            for (int j = 0; j < 4; j++)
                #pragma unroll
                for (int q = 0; q < 4; q++) acc[i][j][q] = 0.f;

        for (int k0 = 0; k0 < K; k0 += 32){
            __syncthreads();
            {   // A tile 128x32
                int gm = bm + aRow;
                bool ok = (gm < M) && (k0 + aK < K);
                const float* src = A + (size_t)gm*K + k0 + aK;
                #pragma unroll
                for (int v = 0; v < 4; v++){
                    float4 f = ok ? *(const float4*)(src + 4*v)
                                  : make_float4(0.f,0.f,0.f,0.f);
                    split4(f, &Ah[aRow][aK + 4*v], &Al[aRow][aK + 4*v]);
                }
            }
            {   // B tile 64x32
                int gn = bn + bRow;
                bool ok = (gn < N) && (k0 + bK < K);
                const float* src = W + (size_t)gn*K + k0 + bK;
                #pragma unroll
                for (int v = 0; v < 2; v++){
                    float4 f = ok ? *(const float4*)(src + 4*v)
                                  : make_float4(0.f,0.f,0.f,0.f);
                    split4(f, &Bh[bRow][bK + 4*v], &Bl[bRow][bK + 4*v]);
                }
            }
            __syncthreads();

            #pragma unroll
            for (int kh = 0; kh < 32; kh += 16){
                unsigned ah[2][4], al[2][4], bh[4][2], bl[4][2];
                #pragma unroll
                for (int mt = 0; mt < 2; mt++){
                    int arow = wm + mt*16 + (t4 & 1)*8 + lr;
                    unsigned off = (unsigned)((arow*40 + kh + (t4 >> 1)*8)*2);
                    ldsm_x4(ah[mt], aHiB + off);
                    ldsm_x4(al[mt], aLoB + off);
                }
                #pragma unroll
                for (int pr = 0; pr < 2; pr++){
                    int brow = wn + pr*16 + (t4 >> 1)*8 + lr;
                    unsigned off = (unsigned)((brow*40 + kh + (t4 & 1)*8)*2);
                    unsigned th[4], tl[4];
                    ldsm_x4(th, bHiB + off);
                    ldsm_x4(tl, bLoB + off);
                    bh[pr*2][0] = th[0]; bh[pr*2][1] = th[1];
                    bh[pr*2+1][0] = th[2]; bh[pr*2+1][1] = th[3];
                    bl[pr*2][0] = tl[0]; bl[pr*2][1] = tl[1];
                    bl[pr*2+1][0] = tl[2]; bl[pr*2+1][1] = tl[3];
                }
                #pragma unroll
                for (int mt = 0; mt < 2; mt++)
                    #pragma unroll
                    for (int nt = 0; nt < 4; nt++){
                        mma_bf16(acc[mt][nt], ah[mt], bh[nt]);
                        mma_bf16(acc[mt][nt], ah[mt], bl[nt]);
                        mma_bf16(acc[mt][nt], al[mt], bh[nt]);
                    }
            }
        }

        #pragma unroll
        for (int mt = 0; mt < 2; mt++)
            #pragma unroll
            for (int nt = 0; nt < 4; nt++){
                int row0 = bm + wm + mt*16 + (lane >> 2);
                int col  = bn + wn + nt*8 + (lane & 3)*2;
                if (col >= N) continue;
                float b0 = bias[col], b1 = bias[col + 1];
                float v0 = acc[mt][nt][0] + b0, v1 = acc[mt][nt][1] + b1;
                float v2 = acc[mt][nt][2] + b0, v3 = acc[mt][nt][3] + b1;
                if (ACT == 1){
                    v0 = gelu_f(v0); v1 = gelu_f(v1);
                    v2 = gelu_f(v2); v3 = gelu_f(v3);
                }
                if (row0 < M){
                    C[(size_t)row0*N + col]     = v0;
                    C[(size_t)row0*N + col + 1] = v1;
                }
                if (row0 + 8 < M){
                    C[(size_t)(row0+8)*N + col]     = v2;
                    C[(size_t)(row0+8)*N + col + 1] = v3;
                }
            }
    }
}

// =============== attention scores: S = scale * Q K^T (MMA) ===============
__global__ __launch_bounds__(256) void mma_scores(){
    const int bh = blockIdx.z;
    const int b = bh >> 3, h = bh & 7;
    const int i0 = blockIdx.y * 128, j0 = blockIdx.x * 64;
    __shared__ __align__(16) __nv_bfloat16 Ah[128][40], Al[128][40];
    __shared__ __align__(16) __nv_bfloat16 Bh[64][40],  Bl[64][40];

    const float* q = g_qkv + ((size_t)b*NTOK)*D + h*EH;
    const float* k = g_qkv + (size_t)MROWS*D + ((size_t)b*NTOK)*D + h*EH;

    const int tid = threadIdx.x;
    const int lane = tid & 31, w = tid >> 5;
    const int wm = (w >> 1)*32, wn = (w & 1)*32;
    const int t4 = lane >> 3, lr = lane & 7;
    const unsigned aHiB = (unsigned)__cvta_generic_to_shared(&Ah[0][0]);
    const unsigned aLoB = (unsigned)__cvta_generic_to_shared(&Al[0][0]);
    const unsigned bHiB = (unsigned)__cvta_generic_to_shared(&Bh[0][0]);
    const unsigned bLoB = (unsigned)__cvta_generic_to_shared(&Bl[0][0]);

    {   // Q tile 128x32
        int row = tid >> 1, kq = (tid & 1)*16;
        int gi = i0 + row;
        const float* src = q + (size_t)gi*D + kq;
        #pragma unroll
        for (int v = 0; v < 4; v++){
            float4 f = (gi < NTOK) ? *(const float4*)(src + 4*v)
                                   : make_float4(0.f,0.f,0.f,0.f);
            split4(f, &Ah[row][kq + 4*v], &Al[row][kq + 4*v]);
        }
    }
    {   // K tile 64x32
        int row = tid >> 2, kq = (tid & 3)*8;
        int gj = j0 + row;
        const float* src = k + (size_t)gj*D + kq;
        #pragma unroll
        for (int v = 0; v < 2; v++){
            float4 f = (gj < NTOK) ? *(const float4*)(src + 4*v)
                                   : make_float4(0.f,0.f,0.f,0.f);
            split4(f, &Bh[row][kq + 4*v], &Bl[row][kq + 4*v]);
        }
    }
    __syncthreads();

    float acc[2][4][4];
    #pragma unroll
    for (int i = 0; i < 2; i++)
        #pragma unroll
        for (int j = 0; j < 4; j++)
            #pragma unroll
            for (int qd = 0; qd < 4; qd++) acc[i][j][qd] = 0.f;

    #pragma unroll
    for (int kh = 0; kh < 32; kh += 16){
        unsigned ah[2][4], al[2][4], bh[4][2], bl[4][2];
        #pragma unroll
        for (int mt = 0; mt < 2; mt++){
            int arow = wm + mt*16 + (t4 & 1)*8 + lr;
            unsigned off = (unsigned)((arow*40 + kh + (t4 >> 1)*8)*2);
            ldsm_x4(ah[mt], aHiB + off);
            ldsm_x4(al[mt], aLoB + off);
        }
        #pragma unroll
        for (int pr = 0; pr < 2; pr++){
            int brow = wn + pr*16 + (t4 >> 1)*8 + lr;
            unsigned off = (unsigned)((brow*40 + kh + (t4 & 1)*8)*2);
            unsigned th[4], tl[4];
            ldsm_x4(th, bHiB + off);
            ldsm_x4(tl, bLoB + off);
            bh[pr*2][0] = th[0]; bh[pr*2][1] = th[1];
            bh[pr*2+1][0] = th[2]; bh[pr*2+1][1] = th[3];
            bl[pr*2][0] = tl[0]; bl[pr*2][1] = tl[1];
            bl[pr*2+1][0] = tl[2]; bl[pr*2+1][1] = tl[3];
        }
        #pragma unroll
        for (int mt = 0; mt < 2; mt++)
            #pragma unroll
            for (int nt = 0; nt < 4; nt++){
                mma_bf16(acc[mt][nt], ah[mt], bh[nt]);
                mma_bf16(acc[mt][nt], ah[mt], bl[nt]);
                mma_bf16(acc[mt][nt], al[mt], bh[nt]);
            }
    }

    float* S = g_scores + (size_t)bh*NTOK*SLD;
    const float scale = 0.17677669529663688f;  // 1/sqrt(32)
    #pragma unroll
    for (int mt = 0; mt < 2; mt++)
        #pragma unroll
        for (int nt = 0; nt < 4; nt++){
            int row0 = i0 + wm + mt*16 + (lane >> 2);
            int col  = j0 + wn + nt*8 + (lane & 3)*2;
            if (col >= NTOK) continue;
            if (row0 < NTOK){
                S[(size_t)row0*SLD + col]     = acc[mt][nt][0]*scale;
                S[(size_t)row0*SLD + col + 1] = acc[mt][nt][1]*scale;
            }
            if (row0 + 8 < NTOK){
                S[(size_t)(row0+8)*SLD + col]     = acc[mt][nt][2]*scale;
                S[(size_t)(row0+8)*SLD + col + 1] = acc[mt][nt][3]*scale;
            }
        }
}

// =============== softmax over last dim (rows of 866, stride 896) =========
__global__ __launch_bounds__(128) void softmax_kernel(){
    size_t row = blockIdx.x;
    float* p = g_scores + row*(size_t)SLD;
    float v[7];
    float mx = -1e30f;
    #pragma unroll
    for (int i = 0; i < 7; i++){
        int j = threadIdx.x + i*128;
        v[i] = (j < NTOK) ? p[j] : -1e30f;
        mx = fmaxf(mx, v[i]);
    }
    mx = blockReduce(mx, true);
    float sum = 0.f;
    #pragma unroll
    for (int i = 0; i < 7; i++){
        v[i] = expf(v[i] - mx);
        sum += v[i];
    }
    sum = blockReduce(sum, false);
    float inv = 1.f / sum;
    #pragma unroll
    for (int i = 0; i < 7; i++){
        int j = threadIdx.x + i*128;
        if (j < NTOK) p[j] = v[i]*inv;
    }
}

// =============== att = P @ V (MMA, V via ldmatrix.trans) ==================
__global__ __launch_bounds__(256) void mma_av(){
    const int bh = blockIdx.y;
    const int b = bh >> 3, h = bh & 7;
    const int i0 = blockIdx.x * 128;
    __shared__ __align__(16) __nv_bfloat16 Ph[128][40], Pl[128][40];
    __shared__ __align__(16) __nv_bfloat16 Vh[32][40],  Vl[32][40];

    const float* S = g_scores + (size_t)bh*NTOK*SLD;
    const float* v = g_qkv + 2*(size_t)MROWS*D + ((size_t)b*NTOK)*D + h*EH;

    const int tid = threadIdx.x;
    const int lane = tid & 31, w = tid >> 5;
    const int t4 = lane >> 3, lr = lane & 7;
    const unsigned pHiB = (unsigned)__cvta_generic_to_shared(&Ph[0][0]);
    const unsigned pLoB = (unsigned)__cvta_generic_to_shared(&Pl[0][0]);
    const unsigned vHiB = (unsigned)__cvta_generic_to_shared(&Vh[0][0]);
    const unsigned vLoB = (unsigned)__cvta_generic_to_shared(&Vl[0][0]);

    float acc[4][4];
    #pragma unroll
    for (int j = 0; j < 4; j++)
        #pragma unroll
        for (int q = 0; q < 4; q++) acc[j][q] = 0.f;

    const int pRow = tid >> 1, pK = (tid & 1)*16;
    const int vRow = tid >> 3, vN = (tid & 7)*4;

    for (int k0 = 0; k0 < NTOK; k0 += 32){
        __syncthreads();
        {   // P tile 128x32
            int gi = i0 + pRow;
            const float* src = S + (size_t)gi*SLD + k0 + pK;
            if (gi < NTOK && k0 + pK + 16 <= NTOK){
                #pragma unroll
                for (int vv = 0; vv < 4; vv++){
                    float4 f = *(const float4*)(src + 4*vv);
                    split4(f, &Ph[pRow][pK + 4*vv], &Pl[pRow][pK + 4*vv]);
                }
            } else {
                #pragma unroll
                for (int vv = 0; vv < 4; vv++){
                    float4 f;
                    float* fe = (float*)&f;
                    #pragma unroll
                    for (int e = 0; e < 4; e++){
                        int kk = k0 + pK + 4*vv + e;
                        fe[e] = (gi < NTOK && kk < NTOK) ? src[4*vv + e] : 0.f;
                    }
                    split4(f, &Ph[pRow][pK + 4*vv], &Pl[pRow][pK + 4*vv]);
                }
            }
        }
        {   // V tile 32(k) x 32(n)
            int gk = k0 + vRow;
            float4 f = (gk < NTOK) ? *(const float4*)(v + (size_t)gk*D + vN)
                                   : make_float4(0.f,0.f,0.f,0.f);
            split4(f, &Vh[vRow][vN], &Vl[vRow][vN]);
        }
        __syncthreads();

        #pragma unroll
        for (int kh = 0; kh < 32; kh += 16){
            unsigned ah[4], al[4], bh[4][2], bl[4][2];
            {
                int arow = w*16 + (t4 & 1)*8 + lr;
                unsigned off = (unsigned)((arow*40 + kh + (t4 >> 1)*8)*2);
                ldsm_x4(ah, pHiB + off);
                ldsm_x4(al, pLoB + off);
            }
            #pragma unroll
            for (int pr = 0; pr < 2; pr++){
                int krow = kh + (t4 & 1)*8 + lr;
                int ncol = pr*16 + (t4 >> 1)*8;
                unsigned off = (unsigned)((krow*40 + ncol)*2);
                unsigned th[4], tl[4];
                ldsm_x4t(th, vHiB + off);
                ldsm_x4t(tl, vLoB + off);
                bh[pr*2][0] = th[0]; bh[pr*2][1] = th[1];
                bh[pr*2+1][0] = th[2]; bh[pr*2+1][1] = th[3];
                bl[pr*2][0] = tl[0]; bl[pr*2][1] = tl[1];
                bl[pr*2+1][0] = tl[2]; bl[pr*2+1][1] = tl[3];
            }
            #pragma unroll
            for (int nt = 0; nt < 4; nt++){
                mma_bf16(acc[nt], ah, bh[nt]);
                mma_bf16(acc[nt], ah, bl[nt]);
                mma_bf16(acc[nt], al, bh[nt]);
            }
        }
    }

    #pragma unroll
    for (int nt = 0; nt < 4; nt++){
        int row0 = i0 + w*16 + (lane >> 2);
        int col  = nt*8 + (lane & 3)*2;
        if (row0 < NTOK){
            float* dst = g_att + ((size_t)b*NTOK + row0)*D + h*EH + col;
            dst[0] = acc[nt][0]; dst[1] = acc[nt][1];
        }
        if (row0 + 8 < NTOK){
            float* dst = g_att + ((size_t)b*NTOK + row0 + 8)*D + h*EH + col;
            dst[0] = acc[nt][2]; dst[1] = acc[nt][3];
        }
    }
}

// ---------------- LayerNorm(x [- sub]) over D=256 ----------------
__global__ __launch_bounds__(256) void ln_kernel(const float* __restrict__ X,
                                                 const float* __restrict__ Sub,
                                                 const float* __restrict__ g,
                                                 const float* __restrict__ beta,
                                                 float* __restrict__ Out){
    int row = blockIdx.x, d = threadIdx.x;
    size_t i = (size_t)row*D + d;
    float v = X[i] - (Sub ? Sub[i] : 0.f);
    float mean = blockReduce(v, false) * (1.f/D);
    float dv = v - mean;
    float var = blockReduce(dv*dv, false) * (1.f/D);
    Out[i] = dv * rsqrtf(var + EPS) * g[d] + beta[d];
}

// ---------------- elementwise fusion kernels ----------------
__global__ void sub_kernel(const float* __restrict__ a, const float* __restrict__ b,
                           float* __restrict__ c, size_t n){
    size_t i = (size_t)blockIdx.x*blockDim.x + threadIdx.x;
    if (i < n) c[i] = a[i] - b[i];
}

__global__ void glu_kernel(const float* __restrict__ a, const float* __restrict__ b,
                           float* __restrict__ c, size_t n){
    size_t i = (size_t)blockIdx.x*blockDim.x + threadIdx.x;
    if (i < n) c[i] = (1.f/(1.f + expf(-a[i]))) * b[i];
}

__global__ void cat_kernel(const float* __restrict__ xatt, const float* __restrict__ y){
    size_t n = (size_t)MROWS*2*D;
    size_t i = (size_t)blockIdx.x*blockDim.x + threadIdx.x;
    if (i >= n) return;
    int c = (int)(i % (2*D));
    size_t r = i / (2*D);
    g_cat[i] = (c < D) ? xatt[r*D + c] : y[r*D + c - D];
}

__global__ void outcomb_kernel(int l){
    size_t n = (size_t)MROWS*DB;
    size_t i = (size_t)blockIdx.x*blockDim.x + threadIdx.x;
    if (i >= n) return;
    float a = g_o56[i], b = g_o56[n + i];
    float v = (1.f/(1.f + expf(-a))) * b;
    g_out[i] = l ? (v - g_out[i]) : v;
}

// ---------------- final: de-standardize, transpose, 2-scale mean ----------
__global__ void final_kernel(float* __restrict__ out, int t){
    size_t total = (size_t)B_*DB*ENC;
    size_t idx = (size_t)blockIdx.x*blockDim.x + threadIdx.x;
    if (idx >= total) return;
    int n = (int)(idx % ENC);
    size_t r = idx / ENC;
    int p = (int)(r % DB);
    int b = (int)(r / DB);
    float v = g_out[((size_t)b*NTOK + n)*DB + p] * g_std[b*ENC + n] + g_mean[b*ENC + n];
    v *= 0.5f;
    if (t == 0) out[idx] = v; else out[idx] += v;
}

// ---------------- host ----------------
static inline GemmArgs ga1(const float* A, const float* W, const float* b, float* C){
    GemmArgs g = {};
    g.A[0] = A; g.W[0] = W; g.Bv[0] = b; g.C[0] = C;
    return g;
}
static inline int gsz(int nt){ return nt < 296 ? nt : 296; }

extern "C" void kernel_launch(void* const* d_in, const int* in_sizes, int n_in,
                              void* d_out, int out_size){
    const float* mbx  = (const float*)d_in[0];
    const float* mbxm = (const float*)d_in[1];
    const float* embW = (const float*)d_in[4];
    const float* embB = (const float*)d_in[5];
    const float* Wq = (const float*)d_in[6];
    const float* Wk = (const float*)d_in[7];
    const float* Wv = (const float*)d_in[8];
    const float* Wo = (const float*)d_in[9];
    const float* W3 = (const float*)d_in[10];
    const float* W4 = (const float*)d_in[11];
    const float* bq = (const float*)d_in[12];
    const float* bk = (const float*)d_in[13];
    const float* bv = (const float*)d_in[14];
    const float* bo = (const float*)d_in[15];
    const float* b3 = (const float*)d_in[16];
    const float* b4 = (const float*)d_in[17];
    const float* W1 = (const float*)d_in[18];
    const float* b1 = (const float*)d_in[19];
    const float* W2 = (const float*)d_in[20];
    const float* b2 = (const float*)d_in[21];
    const float* W5 = (const float*)d_in[22];
    const float* b5 = (const float*)d_in[23];
    const float* W6 = (const float*)d_in[24];
    const float* b6 = (const float*)d_in[25];
    const float* ln1g = (const float*)d_in[26];
    const float* ln1b = (const float*)d_in[27];
    const float* ln2g = (const float*)d_in[28];
    const float* ln2b = (const float*)d_in[29];
    float* out = (float*)d_out;

    float *xin, *h, *qkv, *att, *xatt, *xln, *y1, *y, *xs, *hh, *cat, *o56;
    cudaGetSymbolAddress((void**)&xin,  g_xin);
    cudaGetSymbolAddress((void**)&h,    g_h);
    cudaGetSymbolAddress((void**)&qkv,  g_qkv);
    cudaGetSymbolAddress((void**)&att,  g_att);
    cudaGetSymbolAddress((void**)&xatt, g_xatt);
    cudaGetSymbolAddress((void**)&xln,  g_xln);
    cudaGetSymbolAddress((void**)&y1,   g_y1);
    cudaGetSymbolAddress((void**)&y,    g_y);
    cudaGetSymbolAddress((void**)&xs,   g_xs);
    cudaGetSymbolAddress((void**)&hh,   g_hh);
    cudaGetSymbolAddress((void**)&cat,  g_cat);
    cudaGetSymbolAddress((void**)&o56,  g_o56);

    const size_t MD = (size_t)MROWS*D;
    const int tm = 55;   // ceil(6928/128)

    for (int t = 0; t < TS; t++){
        stats_kernel<<<dim3((ENC + 255)/256, B_), 256>>>(mbx, t);
        {
            size_t n = (size_t)B_*NTOK*SEQ;
            xin_kernel<<<(unsigned)((n + 255)/256), 256>>>(mbx, mbxm, t);
        }
        // embed: M=6928, N=256, K=720
        mma_gemm<0><<<gsz(tm*4), 256>>>(ga1(xin, embW, embB, h),
                                        MROWS, D, SEQ, tm, 4, tm*4);

        for (int l = 0; l < LAYERS; l++){
            // Q, K, V in one launch
            GemmArgs q3 = {};
            q3.A[0] = h; q3.A[1] = h; q3.A[2] = h;
            q3.W[0] = Wq + (size_t)l*D*D; q3.W[1] = Wk + (size_t)l*D*D; q3.W[2] = Wv + (size_t)l*D*D;
            q3.Bv[0] = bq + l*D; q3.Bv[1] = bk + l*D; q3.Bv[2] = bv + l*D;
            q3.C[0] = qkv; q3.C[1] = qkv + MD; q3.C[2] = qkv + 2*MD;
            mma_gemm<0><<<gsz(tm*4*3), 256>>>(q3, MROWS, D, D, tm, 4, tm*4*3);

            mma_scores<<<dim3(14, 7, B_*NH), 256>>>();
            softmax_kernel<<<B_*NH*NTOK, 128>>>();
            mma_av<<<dim3(7, B_*NH), 256>>>();

            mma_gemm<0><<<gsz(tm*4), 256>>>(
                ga1(att, Wo + (size_t)l*D*D, bo + l*D, xatt),
                MROWS, D, D, tm, 4, tm*4);

            ln_kernel<<<MROWS, 256>>>(h, xatt, ln1g + l*D, ln1b + l*D, xln);

            mma_gemm<1><<<gsz(tm*8), 256>>>(
                ga1(xln, W1 + (size_t)l*DFF*D, b1 + l*DFF, y1),
                MROWS, DFF, D, tm, 8, tm*8);
            mma_gemm<0><<<gsz(tm*4), 256>>>(
                ga1(y1, W2 + (size_t)l*D*DFF, b2 + l*D, y),
                MROWS, D, DFF, tm, 4, tm*4);

            sub_kernel<<<(unsigned)((MD + 255)/256), 256>>>(xln, y, xs, MD);

            GemmArgs g34 = {};
            g34.A[0] = xs; g34.A[1] = xs;
            g34.W[0] = W3 + (size_t)l*D*D; g34.W[1] = W4 + (size_t)l*D*D;
            g34.Bv[0] = b3 + l*D; g34.Bv[1] = b4 + l*D;
            g34.C[0] = qkv; g34.C[1] = qkv + MD;   // reuse q/k slots
            mma_gemm<0><<<gsz(tm*4*2), 256>>>(g34, MROWS, D, D, tm, 4, tm*4*2);

            glu_kernel<<<(unsigned)((MD + 255)/256), 256>>>(qkv, qkv + MD, hh, MD);
            cat_kernel<<<(unsigned)(((size_t)MROWS*2*D + 255)/256), 256>>>(xatt, y);

            GemmArgs g56 = {};
            g56.A[0] = cat; g56.A[1] = cat;
            g56.W[0] = W5 + (size_t)l*DB*2*D; g56.W[1] = W6 + (size_t)l*DB*2*D;
            g56.Bv[0] = b5 + l*DB; g56.Bv[1] = b6 + l*DB;
            g56.C[0] = o56; g56.C[1] = o56 + (size_t)MROWS*DB;
            mma_gemm<0><<<gsz(tm*12*2), 256>>>(g56, MROWS, DB, 2*D, tm, 12, tm*12*2);

            outcomb_kernel<<<(unsigned)(((size_t)MROWS*DB + 255)/256), 256>>>(l);

            ln_kernel<<<MROWS, 256>>>(hh, (const float*)nullptr, ln2g + l*D, ln2b + l*D, h);
        }

        final_kernel<<<(unsigned)(((size_t)B_*DB*ENC + 255)/256), 256>>>(out, t);
    }
}

// round 6
// speedup vs baseline: 3.0635x; 1.8328x over previous
#include <cuda_runtime.h>
#include <cuda_bf16.h>
#include <math.h>

#define B_    8
#define TS    2
#define SEQ   720
#define SEQP  736
#define ENC   862
#define MARKD 4
#define NTOK  866
#define D     256
#define NH    8
#define EH    32
#define DFF   512
#define DB    720
#define LAYERS 2
#define EPS   1e-5f
#define MROWS (B_*NTOK)   // 6928
#define MD    ((size_t)MROWS*D)
#define SLD   896
#define SCN   ((size_t)B_*NH*NTOK*SLD)
#define CN    ((size_t)MROWS*2*D)

typedef __nv_bfloat16 bf16;

// ---------------- fp32 scratch ----------------
__device__ float g_mean[B_*ENC], g_std[B_*ENC];
__device__ float g_h[MD], g_xatt[MD], g_xln[MD], g_y[MD], g_hh[MD];
__device__ float g_g34[2*MD];
__device__ float g_o56[(size_t)2*MROWS*DB];
__device__ float g_out[(size_t)MROWS*DB];
__device__ float g_scores[SCN];

// ---------------- bf16 hi/lo planes (lo at +n) ----------------
__device__ __align__(16) bf16 p_xin[2*(size_t)MROWS*SEQP];
__device__ __align__(16) bf16 p_h  [2*MD];
__device__ __align__(16) bf16 p_qkv[2*3*MD];
__device__ __align__(16) bf16 p_att[2*MD];
__device__ __align__(16) bf16 p_xln[2*MD];
__device__ __align__(16) bf16 p_y1 [2*(size_t)MROWS*DFF];
__device__ __align__(16) bf16 p_xs [2*MD];
__device__ __align__(16) bf16 p_cat[2*CN];
__device__ __align__(16) bf16 p_sco[2*SCN];
// weights
__device__ __align__(16) bf16 p_embW[2*256*SEQP];
__device__ __align__(16) bf16 p_Wq[2*LAYERS*D*D], p_Wk[2*LAYERS*D*D], p_Wv[2*LAYERS*D*D];
__device__ __align__(16) bf16 p_Wo[2*LAYERS*D*D], p_W3[2*LAYERS*D*D], p_W4[2*LAYERS*D*D];
__device__ __align__(16) bf16 p_W1[2*LAYERS*DFF*D], p_W2[2*LAYERS*D*DFF];
__device__ __align__(16) bf16 p_W5[2*LAYERS*DB*2*D], p_W6[2*LAYERS*DB*2*D];

// ---------------- helpers ----------------
__device__ __forceinline__ void splitv(float x, bf16& h, bf16& l){
    h = __float2bfloat16(x);
    l = __float2bfloat16(x - __bfloat162float(h));
}
__device__ __forceinline__ void mma_bf16(float c[4], const unsigned a[4], const unsigned b[2]){
    asm volatile("mma.sync.aligned.m16n8k16.row.col.f32.bf16.bf16.f32 "
                 "{%0,%1,%2,%3}, {%4,%5,%6,%7}, {%8,%9}, {%0,%1,%2,%3};\n"
                 : "+f"(c[0]), "+f"(c[1]), "+f"(c[2]), "+f"(c[3])
                 : "r"(a[0]), "r"(a[1]), "r"(a[2]), "r"(a[3]),
                   "r"(b[0]), "r"(b[1]));
}
__device__ __forceinline__ void ldsm_x4(unsigned r[4], unsigned addr){
    asm volatile("ldmatrix.sync.aligned.m8n8.x4.shared.b16 {%0,%1,%2,%3}, [%4];\n"
                 : "=r"(r[0]), "=r"(r[1]), "=r"(r[2]), "=r"(r[3]) : "r"(addr));
}
__device__ __forceinline__ void ldsm_x4t(unsigned r[4], unsigned addr){
    asm volatile("ldmatrix.sync.aligned.m8n8.x4.trans.shared.b16 {%0,%1,%2,%3}, [%4];\n"
                 : "=r"(r[0]), "=r"(r[1]), "=r"(r[2]), "=r"(r[3]) : "r"(addr));
}
__device__ __forceinline__ void cp16(unsigned dst, const void* src, bool p){
    int sz = p ? 16 : 0;
    asm volatile("cp.async.cg.shared.global [%0], [%1], 16, %2;\n"
                 :: "r"(dst), "l"(src), "r"(sz));
}
__device__ __forceinline__ void cpcommit(){ asm volatile("cp.async.commit_group;\n"); }
template<int N> __device__ __forceinline__ void cpwait(){
    asm volatile("cp.async.wait_group %0;\n" :: "n"(N));
}
__device__ __forceinline__ float gelu_f(float x){
    return 0.5f*x*(1.f + erff(x*0.70710678118654752f));
}
__device__ __forceinline__ float blockReduce(float v, bool domax){
    __shared__ float sh[33];
    int lane = threadIdx.x & 31, wid = threadIdx.x >> 5;
    __syncthreads();
    #pragma unroll
    for (int o = 16; o; o >>= 1){
        float ov = __shfl_down_sync(0xffffffffu, v, o);
        v = domax ? fmaxf(v, ov) : (v + ov);
    }
    if (lane == 0) sh[wid] = v;
    __syncthreads();
    if (wid == 0){
        int nw = blockDim.x >> 5;
        v = (lane < nw) ? sh[lane] : (domax ? -1e30f : 0.f);
        #pragma unroll
        for (int o = 16; o; o >>= 1){
            float ov = __shfl_down_sync(0xffffffffu, v, o);
            v = domax ? fmaxf(v, ov) : (v + ov);
        }
        if (lane == 0) sh[32] = v;
    }
    __syncthreads();
    return sh[32];
}

// ---------------- weight split ----------------
__global__ void wsplit(const float* __restrict__ s, bf16* __restrict__ h,
                       bf16* __restrict__ l, size_t n){
    size_t i = (size_t)blockIdx.x*blockDim.x + threadIdx.x;
    if (i < n) splitv(s[i], h[i], l[i]);
}
__global__ void wsplit_pad(const float* __restrict__ s, bf16* __restrict__ h,
                           bf16* __restrict__ l, int rows, int K, int Kp){
    size_t i = (size_t)blockIdx.x*blockDim.x + threadIdx.x;
    size_t total = (size_t)rows*Kp;
    if (i >= total) return;
    int c = (int)(i % Kp); int r = (int)(i / Kp);
    float v = (c < K) ? s[(size_t)r*K + c] : 0.f;
    splitv(v, h[i], l[i]);
}

// ---------------- input standardization ----------------
__global__ void stats_kernel(const float* __restrict__ mbx, int t){
    int b = blockIdx.y;
    int n = blockIdx.x * blockDim.x + threadIdx.x;
    if (n >= ENC) return;
    const float* base = mbx + ((size_t)(b*TS + t)*SEQ)*ENC + n;
    float s = 0.f, ss = 0.f;
    for (int i = 0; i < SEQ; i++){
        float v = base[(size_t)i*ENC];
        s += v; ss += v*v;
    }
    float m = s * (1.f/SEQ);
    float var = ss * (1.f/SEQ) - m*m;
    g_mean[b*ENC + n] = m;
    g_std [b*ENC + n] = sqrtf(var + EPS);
}

__global__ void xin_kernel(const float* __restrict__ mbx,
                           const float* __restrict__ mbxm, int t){
    size_t total = (size_t)MROWS*SEQP;
    size_t idx = (size_t)blockIdx.x*blockDim.x + threadIdx.x;
    if (idx >= total) return;
    int s = (int)(idx % SEQP);
    size_t r = idx / SEQP;
    int n = (int)(r % NTOK);
    int b = (int)(r / NTOK);
    float v = 0.f;
    if (s < SEQ){
        if (n < ENC){
            v = mbx[((size_t)(b*TS + t)*SEQ + s)*ENC + n];
            v = (v - g_mean[b*ENC + n]) / g_std[b*ENC + n];
        } else {
            v = mbxm[((size_t)(b*TS + t)*SEQ + s)*MARKD + (n - ENC)];
        }
    }
    splitv(v, p_xin[idx], p_xin[total + idx]);
}

// =============== MMA GEMM: C = A @ W^T + bias (bf16 planes, cp.async) =====
struct GemmArgs {
    const bf16 *aH[3], *aL[3], *wH[3], *wL[3];
    const float* bias[3];
    float* C[3];
    bf16 *cH[3], *cL[3];
};

template<int ACT>
__global__ __launch_bounds__(256)
void mma_gemm(GemmArgs p, int M, int N, int K, int tilesN, int tpz, int nTiles){
    extern __shared__ __align__(16) char smraw[];
    bf16* sAh = (bf16*)smraw;            // [2][128][40]
    bf16* sAl = sAh + 2*128*40;
    bf16* sBh = sAl + 2*128*40;          // [2][64][40]
    bf16* sBl = sBh + 2*64*40;
    const unsigned aHiB = (unsigned)__cvta_generic_to_shared(sAh);
    const unsigned aLoB = (unsigned)__cvta_generic_to_shared(sAl);
    const unsigned bHiB = (unsigned)__cvta_generic_to_shared(sBh);
    const unsigned bLoB = (unsigned)__cvta_generic_to_shared(sBl);

    const int tid = threadIdx.x;
    const int lane = tid & 31, w = tid >> 5;
    const int wm = (w >> 1)*32, wn = (w & 1)*32;
    const int t4 = lane >> 3, lr = lane & 7;
    const int ldr = tid >> 2, ldc = (tid & 3)*8;

    for (int t = blockIdx.x; t < nTiles; t += gridDim.x){
        const int z  = t / tpz;
        const int rr = t - z*tpz;
        const int bm = (rr / tilesN)*128, bn = (rr % tilesN)*64;
        const bf16* __restrict__ aHp = p.aH[z];
        const bf16* __restrict__ aLp = p.aL[z];
        const bf16* __restrict__ wHp = p.wH[z];
        const bf16* __restrict__ wLp = p.wL[z];
        const float* __restrict__ bias = p.bias[z];
        float* Cp = p.C[z];
        bf16* cHp = p.cH[z];
        bf16* cLp = p.cL[z];

        float acc[2][4][4];
        #pragma unroll
        for (int i = 0; i < 2; i++)
            #pragma unroll
            for (int j = 0; j < 4; j++)
                #pragma unroll
                for (int q = 0; q < 4; q++) acc[i][j][q] = 0.f;

        auto loadst = [&](int s, int k0){
            #pragma unroll
            for (int rep = 0; rep < 2; rep++){
                int r = ldr + rep*64;
                int gm = bm + r;
                bool pr = gm < M;
                size_t so = (size_t)(pr ? gm : 0)*K + k0 + ldc;
                unsigned doff = (unsigned)(((s*128 + r)*40 + ldc)*2);
                cp16(aHiB + doff, aHp + so, pr);
                cp16(aLoB + doff, aLp + so, pr);
            }
            {
                int gn = bn + ldr;
                bool pn = gn < N;
                size_t so = (size_t)(pn ? gn : 0)*K + k0 + ldc;
                unsigned doff = (unsigned)(((s*64 + ldr)*40 + ldc)*2);
                cp16(bHiB + doff, wHp + so, pn);
                cp16(bLoB + doff, wLp + so, pn);
            }
            cpcommit();
        };

        loadst(0, 0);
        int buf = 0;
        const int KT = K >> 5;
        for (int kt = 0; kt < KT; kt++){
            if (kt + 1 < KT){ loadst(buf ^ 1, (kt+1)*32); cpwait<1>(); }
            else cpwait<0>();
            __syncthreads();

            #pragma unroll
            for (int kh = 0; kh < 32; kh += 16){
                unsigned ah[2][4], al[2][4], bh[4][2], bl[4][2];
                #pragma unroll
                for (int mt = 0; mt < 2; mt++){
                    int arow = wm + mt*16 + (t4 & 1)*8 + lr;
                    unsigned off = (unsigned)((((buf*128) + arow)*40 + kh + (t4 >> 1)*8)*2);
                    ldsm_x4(ah[mt], aHiB + off);
                    ldsm_x4(al[mt], aLoB + off);
                }
                #pragma unroll
                for (int pr2 = 0; pr2 < 2; pr2++){
                    int brow = wn + pr2*16 + (t4 >> 1)*8 + lr;
                    unsigned off = (unsigned)((((buf*64) + brow)*40 + kh + (t4 & 1)*8)*2);
                    unsigned th[4], tl[4];
                    ldsm_x4(th, bHiB + off);
                    ldsm_x4(tl, bLoB + off);
                    bh[pr2*2][0] = th[0]; bh[pr2*2][1] = th[1];
                    bh[pr2*2+1][0] = th[2]; bh[pr2*2+1][1] = th[3];
                    bl[pr2*2][0] = tl[0]; bl[pr2*2][1] = tl[1];
                    bl[pr2*2+1][0] = tl[2]; bl[pr2*2+1][1] = tl[3];
                }
                #pragma unroll
                for (int mt = 0; mt < 2; mt++)
                    #pragma unroll
                    for (int nt = 0; nt < 4; nt++){
                        mma_bf16(acc[mt][nt], ah[mt], bh[nt]);
                        mma_bf16(acc[mt][nt], ah[mt], bl[nt]);
                        mma_bf16(acc[mt][nt], al[mt], bh[nt]);
                    }
            }
            __syncthreads();
            buf ^= 1;
        }

        #pragma unroll
        for (int mt = 0; mt < 2; mt++)
            #pragma unroll
            for (int nt = 0; nt < 4; nt++){
                int row0 = bm + wm + mt*16 + (lane >> 2);
                int col  = bn + wn + nt*8 + (lane & 3)*2;
                if (col >= N) continue;
                float b0 = bias[col], b1 = bias[col + 1];
                float v0 = acc[mt][nt][0] + b0, v1 = acc[mt][nt][1] + b1;
                float v2 = acc[mt][nt][2] + b0, v3 = acc[mt][nt][3] + b1;
                if (ACT == 1){
                    v0 = gelu_f(v0); v1 = gelu_f(v1);
                    v2 = gelu_f(v2); v3 = gelu_f(v3);
                }
                if (row0 < M){
                    if (Cp){
                        Cp[(size_t)row0*N + col]     = v0;
                        Cp[(size_t)row0*N + col + 1] = v1;
                    }
                    if (cHp){
                        bf16 h0,l0,h1,l1; splitv(v0,h0,l0); splitv(v1,h1,l1);
                        *(__nv_bfloat162*)(cHp + (size_t)row0*N + col) = __halves2bfloat162(h0,h1);
                        *(__nv_bfloat162*)(cLp + (size_t)row0*N + col) = __halves2bfloat162(l0,l1);
                    }
                }
                if (row0 + 8 < M){
                    if (Cp){
                        Cp[(size_t)(row0+8)*N + col]     = v2;
                        Cp[(size_t)(row0+8)*N + col + 1] = v3;
                    }
                    if (cHp){
                        bf16 h2,l2,h3,l3; splitv(v2,h2,l2); splitv(v3,h3,l3);
                        *(__nv_bfloat162*)(cHp + (size_t)(row0+8)*N + col) = __halves2bfloat162(h2,h3);
                        *(__nv_bfloat162*)(cLp + (size_t)(row0+8)*N + col) = __halves2bfloat162(l2,l3);
                    }
                }
            }
    }
}

// =============== attention scores: S = scale * Q K^T =====================
__global__ __launch_bounds__(256) void mma_scores(){
    const int bh = blockIdx.z;
    const int b = bh >> 3, h = bh & 7;
    const int i0 = blockIdx.y * 128, j0 = blockIdx.x * 64;
    __shared__ __align__(16) bf16 Qh[128][40], Ql[128][40];
    __shared__ __align__(16) bf16 Kh[64][40],  Kl[64][40];

    const bf16* qH = p_qkv + (size_t)b*NTOK*D + h*EH;
    const bf16* qL = qH + 3*MD;
    const bf16* kH = p_qkv + MD + (size_t)b*NTOK*D + h*EH;
    const bf16* kL = kH + 3*MD;

    const int tid = threadIdx.x;
    const int lane = tid & 31, w = tid >> 5;
    const int wm = (w >> 1)*32, wn = (w & 1)*32;
    const int t4 = lane >> 3, lr = lane & 7;
    const unsigned aHiB = (unsigned)__cvta_generic_to_shared(&Qh[0][0]);
    const unsigned aLoB = (unsigned)__cvta_generic_to_shared(&Ql[0][0]);
    const unsigned bHiB = (unsigned)__cvta_generic_to_shared(&Kh[0][0]);
    const unsigned bLoB = (unsigned)__cvta_generic_to_shared(&Kl[0][0]);

    const float4 z4 = make_float4(0.f,0.f,0.f,0.f);
    {   // Q tile 128x32 (two 16B chunks per plane per thread)
        int row = tid >> 1, c = (tid & 1)*16;
        int gi = i0 + row;
        bool ok = gi < NTOK;
        size_t so = (size_t)(ok ? gi : 0)*D + c;
        float4 f0 = ok ? *(const float4*)(qH + so)     : z4;
        float4 f1 = ok ? *(const float4*)(qH + so + 8) : z4;
        *(float4*)&Qh[row][c]     = f0;
        *(float4*)&Qh[row][c + 8] = f1;
        f0 = ok ? *(const float4*)(qL + so)     : z4;
        f1 = ok ? *(const float4*)(qL + so + 8) : z4;
        *(float4*)&Ql[row][c]     = f0;
        *(float4*)&Ql[row][c + 8] = f1;
    }
    {   // K tile 64x32
        int row = tid >> 2, c = (tid & 3)*8;
        int gj = j0 + row;
        bool ok = gj < NTOK;
        size_t so = (size_t)(ok ? gj : 0)*D + c;
        *(float4*)&Kh[row][c] = ok ? *(const float4*)(kH + so) : z4;
        *(float4*)&Kl[row][c] = ok ? *(const float4*)(kL + so) : z4;
    }
    __syncthreads();

    float acc[2][4][4];
    #pragma unroll
    for (int i = 0; i < 2; i++)
        #pragma unroll
        for (int j = 0; j < 4; j++)
            #pragma unroll
            for (int q = 0; q < 4; q++) acc[i][j][q] = 0.f;

    #pragma unroll
    for (int kh = 0; kh < 32; kh += 16){
        unsigned ah[2][4], al[2][4], bh[4][2], bl[4][2];
        #pragma unroll
        for (int mt = 0; mt < 2; mt++){
            int arow = wm + mt*16 + (t4 & 1)*8 + lr;
            unsigned off = (unsigned)((arow*40 + kh + (t4 >> 1)*8)*2);
            ldsm_x4(ah[mt], aHiB + off);
            ldsm_x4(al[mt], aLoB + off);
        }
        #pragma unroll
        for (int pr2 = 0; pr2 < 2; pr2++){
            int brow = wn + pr2*16 + (t4 >> 1)*8 + lr;
            unsigned off = (unsigned)((brow*40 + kh + (t4 & 1)*8)*2);
            unsigned th[4], tl[4];
            ldsm_x4(th, bHiB + off);
            ldsm_x4(tl, bLoB + off);
            bh[pr2*2][0] = th[0]; bh[pr2*2][1] = th[1];
            bh[pr2*2+1][0] = th[2]; bh[pr2*2+1][1] = th[3];
            bl[pr2*2][0] = tl[0]; bl[pr2*2][1] = tl[1];
            bl[pr2*2+1][0] = tl[2]; bl[pr2*2+1][1] = tl[3];
        }
        #pragma unroll
        for (int mt = 0; mt < 2; mt++)
            #pragma unroll
            for (int nt = 0; nt < 4; nt++){
                mma_bf16(acc[mt][nt], ah[mt], bh[nt]);
                mma_bf16(acc[mt][nt], ah[mt], bl[nt]);
                mma_bf16(acc[mt][nt], al[mt], bh[nt]);
            }
    }

    float* S = g_scores + (size_t)bh*NTOK*SLD;
    const float scale = 0.17677669529663688f;
    #pragma unroll
    for (int mt = 0; mt < 2; mt++)
        #pragma unroll
        for (int nt = 0; nt < 4; nt++){
            int row0 = i0 + wm + mt*16 + (lane >> 2);
            int col  = j0 + wn + nt*8 + (lane & 3)*2;
            if (col >= NTOK) continue;
            if (row0 < NTOK){
                S[(size_t)row0*SLD + col]     = acc[mt][nt][0]*scale;
                S[(size_t)row0*SLD + col + 1] = acc[mt][nt][1]*scale;
            }
            if (row0 + 8 < NTOK){
                S[(size_t)(row0+8)*SLD + col]     = acc[mt][nt][2]*scale;
                S[(size_t)(row0+8)*SLD + col + 1] = acc[mt][nt][3]*scale;
            }
        }
}

// =============== softmax: fp32 scores -> bf16 hi/lo planes (padded) ======
__global__ __launch_bounds__(128) void softmax_kernel(){
    size_t row = blockIdx.x;
    const float* p = g_scores + row*(size_t)SLD;
    bf16* SH = p_sco + row*(size_t)SLD;
    bf16* SL = SH + SCN;
    float v[7];
    float mx = -1e30f;
    #pragma unroll
    for (int i = 0; i < 7; i++){
        int j = threadIdx.x + i*128;
        v[i] = (j < NTOK) ? p[j] : -1e30f;
        mx = fmaxf(mx, v[i]);
    }
    mx = blockReduce(mx, true);
    float sum = 0.f;
    #pragma unroll
    for (int i = 0; i < 7; i++){
        v[i] = expf(v[i] - mx);
        sum += v[i];
    }
    sum = blockReduce(sum, false);
    float inv = 1.f / sum;
    const bf16 z = __float2bfloat16(0.f);
    #pragma unroll
    for (int i = 0; i < 7; i++){
        int j = threadIdx.x + i*128;
        if (j < NTOK){
            bf16 hh, ll;
            splitv(v[i]*inv, hh, ll);
            SH[j] = hh; SL[j] = ll;
        } else {
            SH[j] = z; SL[j] = z;
        }
    }
}

// =============== att = P @ V (planes, cp.async double buffer) =============
__global__ __launch_bounds__(256) void mma_av(){
    extern __shared__ __align__(16) char smraw[];
    bf16* Ph = (bf16*)smraw;           // [2][128][40]
    bf16* Pl = Ph + 2*128*40;
    bf16* Vh = Pl + 2*128*40;          // [2][32][40]
    bf16* Vl = Vh + 2*32*40;
    const unsigned pHiB = (unsigned)__cvta_generic_to_shared(Ph);
    const unsigned pLoB = (unsigned)__cvta_generic_to_shared(Pl);
    const unsigned vHiB = (unsigned)__cvta_generic_to_shared(Vh);
    const unsigned vLoB = (unsigned)__cvta_generic_to_shared(Vl);

    const int bh = blockIdx.y;
    const int b = bh >> 3, h = bh & 7;
    const int i0 = blockIdx.x * 128;
    const bf16* SH = p_sco + (size_t)bh*NTOK*SLD;
    const bf16* SL = SH + SCN;
    const bf16* vH = p_qkv + 2*MD + (size_t)b*NTOK*D + h*EH;
    const bf16* vL = vH + 3*MD;

    const int tid = threadIdx.x;
    const int lane = tid & 31, w = tid >> 5;
    const int t4 = lane >> 3, lr = lane & 7;
    const int ldr = tid >> 2, ldc = (tid & 3)*8;

    float acc[4][4];
    #pragma unroll
    for (int j = 0; j < 4; j++)
        #pragma unroll
        for (int q = 0; q < 4; q++) acc[j][q] = 0.f;

    auto loadst = [&](int s, int k0){
        #pragma unroll
        for (int rep = 0; rep < 2; rep++){
            int r = ldr + rep*64;
            int gi = i0 + r;
            bool pr = gi < NTOK;
            size_t so = (size_t)(pr ? gi : 0)*SLD + k0 + ldc;
            unsigned doff = (unsigned)(((s*128 + r)*40 + ldc)*2);
            cp16(pHiB + doff, SH + so, pr);
            cp16(pLoB + doff, SL + so, pr);
        }
        if (tid < 128){
            int gk = k0 + ldr;
            bool pk = gk < NTOK;
            size_t so = (size_t)(pk ? gk : 0)*D + ldc;
            unsigned doff = (unsigned)(((s*32 + ldr)*40 + ldc)*2);
            cp16(vHiB + doff, vH + so, pk);
            cp16(vLoB + doff, vL + so, pk);
        }
        cpcommit();
    };

    loadst(0, 0);
    int buf = 0;
    const int KT = SLD / 32;   // 28
    for (int kt = 0; kt < KT; kt++){
        if (kt + 1 < KT){ loadst(buf ^ 1, (kt+1)*32); cpwait<1>(); }
        else cpwait<0>();
        __syncthreads();

        #pragma unroll
        for (int kh = 0; kh < 32; kh += 16){
            unsigned ah[4], al[4], bh2[4][2], bl2[4][2];
            {
                int arow = w*16 + (t4 & 1)*8 + lr;
                unsigned off = (unsigned)((((buf*128) + arow)*40 + kh + (t4 >> 1)*8)*2);
                ldsm_x4(ah, pHiB + off);
                ldsm_x4(al, pLoB + off);
            }
            #pragma unroll
            for (int pr2 = 0; pr2 < 2; pr2++){
                int krow = kh + (t4 & 1)*8 + lr;
                int ncol = pr2*16 + (t4 >> 1)*8;
                unsigned off = (unsigned)((((buf*32) + krow)*40 + ncol)*2);
                unsigned th[4], tl[4];
                ldsm_x4t(th, vHiB + off);
                ldsm_x4t(tl, vLoB + off);
                bh2[pr2*2][0] = th[0]; bh2[pr2*2][1] = th[1];
                bh2[pr2*2+1][0] = th[2]; bh2[pr2*2+1][1] = th[3];
                bl2[pr2*2][0] = tl[0]; bl2[pr2*2][1] = tl[1];
                bl2[pr2*2+1][0] = tl[2]; bl2[pr2*2+1][1] = tl[3];
            }
            #pragma unroll
            for (int nt = 0; nt < 4; nt++){
                mma_bf16(acc[nt], ah, bh2[nt]);
                mma_bf16(acc[nt], ah, bl2[nt]);
                mma_bf16(acc[nt], al, bh2[nt]);
            }
        }
        __syncthreads();
        buf ^= 1;
    }

    #pragma unroll
    for (int nt = 0; nt < 4; nt++){
        int row0 = i0 + w*16 + (lane >> 2);
        int col  = nt*8 + (lane & 3)*2;
        if (row0 < NTOK){
            size_t dst = ((size_t)b*NTOK + row0)*D + h*EH + col;
            bf16 h0,l0,h1,l1; splitv(acc[nt][0],h0,l0); splitv(acc[nt][1],h1,l1);
            *(__nv_bfloat162*)(p_att + dst)      = __halves2bfloat162(h0,h1);
            *(__nv_bfloat162*)(p_att + MD + dst) = __halves2bfloat162(l0,l1);
        }
        if (row0 + 8 < NTOK){
            size_t dst = ((size_t)b*NTOK + row0 + 8)*D + h*EH + col;
            bf16 h2,l2,h3,l3; splitv(acc[nt][2],h2,l2); splitv(acc[nt][3],h3,l3);
            *(__nv_bfloat162*)(p_att + dst)      = __halves2bfloat162(h2,h3);
            *(__nv_bfloat162*)(p_att + MD + dst) = __halves2bfloat162(l2,l3);
        }
    }
}

// ---------------- LayerNorm(x [- sub]) over D=256 (+ optional planes) ----
__global__ __launch_bounds__(256) void ln_kernel(const float* __restrict__ X,
                                                 const float* __restrict__ Sub,
                                                 const float* __restrict__ g,
                                                 const float* __restrict__ beta,
                                                 float* __restrict__ Out,
                                                 bf16* __restrict__ pH,
                                                 bf16* __restrict__ pL){
    int row = blockIdx.x, d = threadIdx.x;
    size_t i = (size_t)row*D + d;
    float v = X[i] - (Sub ? Sub[i] : 0.f);
    float mean = blockReduce(v, false) * (1.f/D);
    float dv = v - mean;
    float var = blockReduce(dv*dv, false) * (1.f/D);
    float o = dv * rsqrtf(var + EPS) * g[d] + beta[d];
    Out[i] = o;
    if (pH){
        bf16 hh, ll; splitv(o, hh, ll);
        pH[i] = hh; pL[i] = ll;
    }
}

// ---------------- elementwise ----------------
__global__ void sub_kernel(const float* __restrict__ a, const float* __restrict__ b){
    size_t i = (size_t)blockIdx.x*blockDim.x + threadIdx.x;
    if (i >= MD) return;
    splitv(a[i] - b[i], p_xs[i], p_xs[MD + i]);
}

__global__ void glu_kernel(const float* __restrict__ a, const float* __restrict__ b,
                           float* __restrict__ c, size_t n){
    size_t i = (size_t)blockIdx.x*blockDim.x + threadIdx.x;
    if (i < n) c[i] = (1.f/(1.f + expf(-a[i]))) * b[i];
}

__global__ void cat_kernel(const float* __restrict__ xatt, const float* __restrict__ y){
    size_t i = (size_t)blockIdx.x*blockDim.x + threadIdx.x;
    if (i >= CN) return;
    int c = (int)(i % (2*D));
    size_t r = i / (2*D);
    float v = (c < D) ? xatt[r*D + c] : y[r*D + c - D];
    splitv(v, p_cat[i], p_cat[CN + i]);
}

__global__ void outcomb_kernel(int l){
    size_t n = (size_t)MROWS*DB;
    size_t i = (size_t)blockIdx.x*blockDim.x + threadIdx.x;
    if (i >= n) return;
    float a = g_o56[i], b = g_o56[n + i];
    float v = (1.f/(1.f + expf(-a))) * b;
    g_out[i] = l ? (v - g_out[i]) : v;
}

__global__ void final_kernel(float* __restrict__ out, int t){
    size_t total = (size_t)B_*DB*ENC;
    size_t idx = (size_t)blockIdx.x*blockDim.x + threadIdx.x;
    if (idx >= total) return;
    int n = (int)(idx % ENC);
    size_t r = idx / ENC;
    int p = (int)(r % DB);
    int b = (int)(r / DB);
    float v = g_out[((size_t)b*NTOK + n)*DB + p] * g_std[b*ENC + n] + g_mean[b*ENC + n];
    v *= 0.5f;
    if (t == 0) out[idx] = v; else out[idx] += v;
}

// ---------------- host ----------------
static inline int gsz(int nt){ return nt < 296 ? nt : 296; }
static void* sym(const void* s){ void* p; cudaGetSymbolAddress(&p, s); return p; }

extern "C" void kernel_launch(void* const* d_in, const int* in_sizes, int n_in,
                              void* d_out, int out_size){
    const float* mbx  = (const float*)d_in[0];
    const float* mbxm = (const float*)d_in[1];
    const float* embW = (const float*)d_in[4];
    const float* embB = (const float*)d_in[5];
    const float* Wq = (const float*)d_in[6];
    const float* Wk = (const float*)d_in[7];
    const float* Wv = (const float*)d_in[8];
    const float* Wo = (const float*)d_in[9];
    const float* W3 = (const float*)d_in[10];
    const float* W4 = (const float*)d_in[11];
    const float* bq = (const float*)d_in[12];
    const float* bk = (const float*)d_in[13];
    const float* bv = (const float*)d_in[14];
    const float* bo = (const float*)d_in[15];
    const float* b3 = (const float*)d_in[16];
    const float* b4 = (const float*)d_in[17];
    const float* W1 = (const float*)d_in[18];
    const float* b1 = (const float*)d_in[19];
    const float* W2 = (const float*)d_in[20];
    const float* b2 = (const float*)d_in[21];
    const float* W5 = (const float*)d_in[22];
    const float* b5 = (const float*)d_in[23];
    const float* W6 = (const float*)d_in[24];
    const float* b6 = (const float*)d_in[25];
    const float* ln1g = (const float*)d_in[26];
    const float* ln1b = (const float*)d_in[27];
    const float* ln2g = (const float*)d_in[28];
    const float* ln2b = (const float*)d_in[29];
    float* out = (float*)d_out;

    // symbol addresses
    float* hF   = (float*)sym(g_h);
    float* xatt = (float*)sym(g_xatt);
    float* xln  = (float*)sym(g_xln);
    float* yF   = (float*)sym(g_y);
    float* hhF  = (float*)sym(g_hh);
    float* g34F = (float*)sym(g_g34);
    float* o56F = (float*)sym(g_o56);

    bf16* xinP = (bf16*)sym(p_xin);
    bf16* hP   = (bf16*)sym(p_h);
    bf16* qkvP = (bf16*)sym(p_qkv);
    bf16* attP = (bf16*)sym(p_att);
    bf16* xlnP = (bf16*)sym(p_xln);
    bf16* y1P  = (bf16*)sym(p_y1);
    bf16* xsP  = (bf16*)sym(p_xs);
    bf16* catP = (bf16*)sym(p_cat);
    bf16* embWP = (bf16*)sym(p_embW);
    bf16* WqP = (bf16*)sym(p_Wq); bf16* WkP = (bf16*)sym(p_Wk);
    bf16* WvP = (bf16*)sym(p_Wv); bf16* WoP = (bf16*)sym(p_Wo);
    bf16* W3P = (bf16*)sym(p_W3); bf16* W4P = (bf16*)sym(p_W4);
    bf16* W1P = (bf16*)sym(p_W1); bf16* W2P = (bf16*)sym(p_W2);
    bf16* W5P = (bf16*)sym(p_W5); bf16* W6P = (bf16*)sym(p_W6);

    const size_t XN  = (size_t)MROWS*SEQP;
    const size_t EWN = (size_t)256*SEQP;
    const size_t WDD = (size_t)LAYERS*D*D;
    const size_t W1N = (size_t)LAYERS*DFF*D;
    const size_t W5N = (size_t)LAYERS*DB*2*D;
    const size_t Y1N = (size_t)MROWS*DFF;

    cudaFuncSetAttribute(mma_gemm<0>, cudaFuncAttributeMaxDynamicSharedMemorySize, 61440);
    cudaFuncSetAttribute(mma_gemm<1>, cudaFuncAttributeMaxDynamicSharedMemorySize, 61440);
    cudaFuncSetAttribute(mma_av,      cudaFuncAttributeMaxDynamicSharedMemorySize, 51200);

    // weight splits (once per call)
    wsplit_pad<<<(unsigned)((EWN + 255)/256), 256>>>(embW, embWP, embWP + EWN, 256, SEQ, SEQP);
    wsplit<<<(unsigned)((WDD + 255)/256), 256>>>(Wq, WqP, WqP + WDD, WDD);
    wsplit<<<(unsigned)((WDD + 255)/256), 256>>>(Wk, WkP, WkP + WDD, WDD);
    wsplit<<<(unsigned)((WDD + 255)/256), 256>>>(Wv, WvP, WvP + WDD, WDD);
    wsplit<<<(unsigned)((WDD + 255)/256), 256>>>(Wo, WoP, WoP + WDD, WDD);
    wsplit<<<(unsigned)((WDD + 255)/256), 256>>>(W3, W3P, W3P + WDD, WDD);
    wsplit<<<(unsigned)((WDD + 255)/256), 256>>>(W4, W4P, W4P + WDD, WDD);
    wsplit<<<(unsigned)((W1N + 255)/256), 256>>>(W1, W1P, W1P + W1N, W1N);
    wsplit<<<(unsigned)((W1N + 255)/256), 256>>>(W2, W2P, W2P + W1N, W1N);
    wsplit<<<(unsigned)((W5N + 255)/256), 256>>>(W5, W5P, W5P + W5N, W5N);
    wsplit<<<(unsigned)((W5N + 255)/256), 256>>>(W6, W6P, W6P + W5N, W5N);

    const int tm = 55;  // ceil(6928/128)

    for (int t = 0; t < TS; t++){
        stats_kernel<<<dim3((ENC + 255)/256, B_), 256>>>(mbx, t);
        xin_kernel<<<(unsigned)((XN + 255)/256), 256>>>(mbx, mbxm, t);

        {   // embed: M=6928, N=256, K=736 -> fp32 h + planes
            GemmArgs a = {};
            a.aH[0] = xinP; a.aL[0] = xinP + XN;
            a.wH[0] = embWP; a.wL[0] = embWP + EWN;
            a.bias[0] = embB; a.C[0] = hF;
            a.cH[0] = hP; a.cL[0] = hP + MD;
            mma_gemm<0><<<gsz(tm*4), 256, 61440>>>(a, MROWS, D, SEQP, 4, tm*4, tm*4);
        }

        for (int l = 0; l < LAYERS; l++){
            {   // QKV -> planes only
                GemmArgs a = {};
                for (int z = 0; z < 3; z++){
                    a.aH[z] = hP; a.aL[z] = hP + MD;
                    a.cH[z] = qkvP + (size_t)z*MD;
                    a.cL[z] = qkvP + 3*MD + (size_t)z*MD;
                }
                a.wH[0] = WqP + (size_t)l*D*D; a.wL[0] = WqP + WDD + (size_t)l*D*D;
                a.wH[1] = WkP + (size_t)l*D*D; a.wL[1] = WkP + WDD + (size_t)l*D*D;
                a.wH[2] = WvP + (size_t)l*D*D; a.wL[2] = WvP + WDD + (size_t)l*D*D;
                a.bias[0] = bq + l*D; a.bias[1] = bk + l*D; a.bias[2] = bv + l*D;
                mma_gemm<0><<<gsz(tm*4*3), 256, 61440>>>(a, MROWS, D, D, 4, tm*4, tm*4*3);
            }

            mma_scores<<<dim3(14, 7, B_*NH), 256>>>();
            softmax_kernel<<<B_*NH*NTOK, 128>>>();
            mma_av<<<dim3(7, B_*NH), 256, 51200>>>();

            {   // Wo: att planes -> fp32 xatt
                GemmArgs a = {};
                a.aH[0] = attP; a.aL[0] = attP + MD;
                a.wH[0] = WoP + (size_t)l*D*D; a.wL[0] = WoP + WDD + (size_t)l*D*D;
                a.bias[0] = bo + l*D; a.C[0] = xatt;
                mma_gemm<0><<<gsz(tm*4), 256, 61440>>>(a, MROWS, D, D, 4, tm*4, tm*4);
            }

            ln_kernel<<<MROWS, 256>>>(hF, xatt, ln1g + l*D, ln1b + l*D, xln,
                                      xlnP, xlnP + MD);

            {   // W1 + GELU -> y1 planes only
                GemmArgs a = {};
                a.aH[0] = xlnP; a.aL[0] = xlnP + MD;
                a.wH[0] = W1P + (size_t)l*DFF*D; a.wL[0] = W1P + W1N + (size_t)l*DFF*D;
                a.bias[0] = b1 + l*DFF;
                a.cH[0] = y1P; a.cL[0] = y1P + Y1N;
                mma_gemm<1><<<gsz(tm*8), 256, 61440>>>(a, MROWS, DFF, D, 8, tm*8, tm*8);
            }
            {   // W2 -> fp32 y
                GemmArgs a = {};
                a.aH[0] = y1P; a.aL[0] = y1P + Y1N;
                a.wH[0] = W2P + (size_t)l*D*DFF; a.wL[0] = W2P + W1N + (size_t)l*D*DFF;
                a.bias[0] = b2 + l*D; a.C[0] = yF;
                mma_gemm<0><<<gsz(tm*4), 256, 61440>>>(a, MROWS, D, DFF, 4, tm*4, tm*4);
            }

            sub_kernel<<<(unsigned)((MD + 255)/256), 256>>>(xln, yF);

            {   // W3/W4 -> fp32 pair in g_g34
                GemmArgs a = {};
                for (int z = 0; z < 2; z++){
                    a.aH[z] = xsP; a.aL[z] = xsP + MD;
                    a.C[z] = g34F + (size_t)z*MD;
                }
                a.wH[0] = W3P + (size_t)l*D*D; a.wL[0] = W3P + WDD + (size_t)l*D*D;
                a.wH[1] = W4P + (size_t)l*D*D; a.wL[1] = W4P + WDD + (size_t)l*D*D;
                a.bias[0] = b3 + l*D; a.bias[1] = b4 + l*D;
                mma_gemm<0><<<gsz(tm*4*2), 256, 61440>>>(a, MROWS, D, D, 4, tm*4, tm*4*2);
            }

            glu_kernel<<<(unsigned)((MD + 255)/256), 256>>>(g34F, g34F + MD, hhF, MD);
            cat_kernel<<<(unsigned)((CN + 255)/256), 256>>>(xatt, yF);

            {   // W5/W6 -> fp32 pair in g_o56
                GemmArgs a = {};
                for (int z = 0; z < 2; z++){
                    a.aH[z] = catP; a.aL[z] = catP + CN;
                    a.C[z] = o56F + (size_t)z*MROWS*DB;
                }
                a.wH[0] = W5P + (size_t)l*DB*2*D; a.wL[0] = W5P + W5N + (size_t)l*DB*2*D;
                a.wH[1] = W6P + (size_t)l*DB*2*D; a.wL[1] = W6P + W5N + (size_t)l*DB*2*D;
                a.bias[0] = b5 + l*DB; a.bias[1] = b6 + l*DB;
                mma_gemm<0><<<gsz(tm*12*2), 256, 61440>>>(a, MROWS, DB, 2*D, 12, tm*12, tm*12*2);
            }

            outcomb_kernel<<<(unsigned)(((size_t)MROWS*DB + 255)/256), 256>>>(l);

            ln_kernel<<<MROWS, 256>>>(hhF, (const float*)nullptr,
                                      ln2g + l*D, ln2b + l*D, hF, hP, hP + MD);
        }

        final_kernel<<<(unsigned)(((size_t)B_*DB*ENC + 255)/256), 256>>>(out, t);
    }
}

// round 7
// speedup vs baseline: 4.0897x; 1.3350x over previous
#include <cuda_runtime.h>
#include <cuda_bf16.h>
#include <math.h>

#define B_    8
#define TS    2
#define SEQ   720
#define SEQP  736
#define ENC   862
#define MARKD 4
#define NTOK  866
#define D     256
#define NH    8
#define EH    32
#define DFF   512
#define DB    720
#define LAYERS 2
#define EPS   1e-5f
#define MROWS (B_*NTOK)   // 6928
#define MD    ((size_t)MROWS*D)
#define CN    ((size_t)MROWS*2*D)

typedef __nv_bfloat16 bf16;

// ---------------- fp32 scratch ----------------
__device__ float g_mean[B_*ENC], g_std[B_*ENC];
__device__ float g_h[MD], g_xatt[MD], g_xln[MD], g_y[MD], g_hh[MD];
__device__ float g_g34[2*MD];
__device__ float g_o56[(size_t)2*MROWS*DB];
__device__ float g_out[(size_t)MROWS*DB];

// ---------------- bf16 hi/lo planes (lo at +n) ----------------
__device__ __align__(16) bf16 p_xin[2*(size_t)MROWS*SEQP];
__device__ __align__(16) bf16 p_h  [2*MD];
__device__ __align__(16) bf16 p_qkv[2*3*MD];
__device__ __align__(16) bf16 p_att[2*MD];
__device__ __align__(16) bf16 p_xln[2*MD];
__device__ __align__(16) bf16 p_y1 [2*(size_t)MROWS*DFF];
__device__ __align__(16) bf16 p_xs [2*MD];
__device__ __align__(16) bf16 p_cat[2*CN];
// weights
__device__ __align__(16) bf16 p_embW[2*256*SEQP];
__device__ __align__(16) bf16 p_Wq[2*LAYERS*D*D], p_Wk[2*LAYERS*D*D], p_Wv[2*LAYERS*D*D];
__device__ __align__(16) bf16 p_Wo[2*LAYERS*D*D], p_W3[2*LAYERS*D*D], p_W4[2*LAYERS*D*D];
__device__ __align__(16) bf16 p_W1[2*LAYERS*DFF*D], p_W2[2*LAYERS*D*DFF];
__device__ __align__(16) bf16 p_W5[2*LAYERS*DB*2*D], p_W6[2*LAYERS*DB*2*D];

// ---------------- helpers ----------------
__device__ __forceinline__ void splitv(float x, bf16& h, bf16& l){
    h = __float2bfloat16(x);
    l = __float2bfloat16(x - __bfloat162float(h));
}
__device__ __forceinline__ unsigned pack2u(bf16 a, bf16 b){
    __nv_bfloat162 t = __halves2bfloat162(a, b);
    return *(unsigned*)&t;
}
__device__ __forceinline__ void mma_bf16(float c[4], const unsigned a[4], const unsigned b[2]){
    asm volatile("mma.sync.aligned.m16n8k16.row.col.f32.bf16.bf16.f32 "
                 "{%0,%1,%2,%3}, {%4,%5,%6,%7}, {%8,%9}, {%0,%1,%2,%3};\n"
                 : "+f"(c[0]), "+f"(c[1]), "+f"(c[2]), "+f"(c[3])
                 : "r"(a[0]), "r"(a[1]), "r"(a[2]), "r"(a[3]),
                   "r"(b[0]), "r"(b[1]));
}
__device__ __forceinline__ void ldsm_x4(unsigned r[4], unsigned addr){
    asm volatile("ldmatrix.sync.aligned.m8n8.x4.shared.b16 {%0,%1,%2,%3}, [%4];\n"
                 : "=r"(r[0]), "=r"(r[1]), "=r"(r[2]), "=r"(r[3]) : "r"(addr));
}
__device__ __forceinline__ void ldsm_x4t(unsigned r[4], unsigned addr){
    asm volatile("ldmatrix.sync.aligned.m8n8.x4.trans.shared.b16 {%0,%1,%2,%3}, [%4];\n"
                 : "=r"(r[0]), "=r"(r[1]), "=r"(r[2]), "=r"(r[3]) : "r"(addr));
}
__device__ __forceinline__ void cp16(unsigned dst, const void* src, bool p){
    int sz = p ? 16 : 0;
    asm volatile("cp.async.cg.shared.global [%0], [%1], 16, %2;\n"
                 :: "r"(dst), "l"(src), "r"(sz));
}
__device__ __forceinline__ void cpcommit(){ asm volatile("cp.async.commit_group;\n"); }
template<int N> __device__ __forceinline__ void cpwait(){
    asm volatile("cp.async.wait_group %0;\n" :: "n"(N));
}
__device__ __forceinline__ float gelu_f(float x){
    return 0.5f*x*(1.f + erff(x*0.70710678118654752f));
}
__device__ __forceinline__ float blockReduce(float v, bool domax){
    __shared__ float sh[33];
    int lane = threadIdx.x & 31, wid = threadIdx.x >> 5;
    __syncthreads();
    #pragma unroll
    for (int o = 16; o; o >>= 1){
        float ov = __shfl_down_sync(0xffffffffu, v, o);
        v = domax ? fmaxf(v, ov) : (v + ov);
    }
    if (lane == 0) sh[wid] = v;
    __syncthreads();
    if (wid == 0){
        int nw = blockDim.x >> 5;
        v = (lane < nw) ? sh[lane] : (domax ? -1e30f : 0.f);
        #pragma unroll
        for (int o = 16; o; o >>= 1){
            float ov = __shfl_down_sync(0xffffffffu, v, o);
            v = domax ? fmaxf(v, ov) : (v + ov);
        }
        if (lane == 0) sh[32] = v;
    }
    __syncthreads();
    return sh[32];
}

// ---------------- weight split ----------------
__global__ void wsplit(const float* __restrict__ s, bf16* __restrict__ h,
                       bf16* __restrict__ l, size_t n){
    size_t i = (size_t)blockIdx.x*blockDim.x + threadIdx.x;
    if (i < n) splitv(s[i], h[i], l[i]);
}
__global__ void wsplit_pad(const float* __restrict__ s, bf16* __restrict__ h,
                           bf16* __restrict__ l, int rows, int K, int Kp){
    size_t i = (size_t)blockIdx.x*blockDim.x + threadIdx.x;
    size_t total = (size_t)rows*Kp;
    if (i >= total) return;
    int c = (int)(i % Kp); int r = (int)(i / Kp);
    float v = (c < K) ? s[(size_t)r*K + c] : 0.f;
    splitv(v, h[i], l[i]);
}

// ---------------- input standardization ----------------
__global__ void stats_kernel(const float* __restrict__ mbx, int t){
    int b = blockIdx.y;
    int n = blockIdx.x * blockDim.x + threadIdx.x;
    if (n >= ENC) return;
    const float* base = mbx + ((size_t)(b*TS + t)*SEQ)*ENC + n;
    float s = 0.f, ss = 0.f;
    for (int i = 0; i < SEQ; i++){
        float v = base[(size_t)i*ENC];
        s += v; ss += v*v;
    }
    float m = s * (1.f/SEQ);
    float var = ss * (1.f/SEQ) - m*m;
    g_mean[b*ENC + n] = m;
    g_std [b*ENC + n] = sqrtf(var + EPS);
}

__global__ void xin_kernel(const float* __restrict__ mbx,
                           const float* __restrict__ mbxm, int t){
    size_t total = (size_t)MROWS*SEQP;
    size_t idx = (size_t)blockIdx.x*blockDim.x + threadIdx.x;
    if (idx >= total) return;
    int s = (int)(idx % SEQP);
    size_t r = idx / SEQP;
    int n = (int)(r % NTOK);
    int b = (int)(r / NTOK);
    float v = 0.f;
    if (s < SEQ){
        if (n < ENC){
            v = mbx[((size_t)(b*TS + t)*SEQ + s)*ENC + n];
            v = (v - g_mean[b*ENC + n]) / g_std[b*ENC + n];
        } else {
            v = mbxm[((size_t)(b*TS + t)*SEQ + s)*MARKD + (n - ENC)];
        }
    }
    splitv(v, p_xin[idx], p_xin[total + idx]);
}

// =============== MMA GEMM: C = A @ W^T + bias (bf16 planes, cp.async) =====
struct GemmArgs {
    const bf16 *aH[3], *aL[3], *wH[3], *wL[3];
    const float* bias[3];
    float* C[3];
    bf16 *cH[3], *cL[3];
};

template<int ACT>
__global__ __launch_bounds__(256)
void mma_gemm(GemmArgs p, int M, int N, int K, int tilesN, int tpz, int nTiles){
    extern __shared__ __align__(16) char smraw[];
    bf16* sAh = (bf16*)smraw;            // [2][128][40]
    bf16* sAl = sAh + 2*128*40;
    bf16* sBh = sAl + 2*128*40;          // [2][64][40]
    bf16* sBl = sBh + 2*64*40;
    const unsigned aHiB = (unsigned)__cvta_generic_to_shared(sAh);
    const unsigned aLoB = (unsigned)__cvta_generic_to_shared(sAl);
    const unsigned bHiB = (unsigned)__cvta_generic_to_shared(sBh);
    const unsigned bLoB = (unsigned)__cvta_generic_to_shared(sBl);

    const int tid = threadIdx.x;
    const int lane = tid & 31, w = tid >> 5;
    const int wm = (w >> 1)*32, wn = (w & 1)*32;
    const int t4 = lane >> 3, lr = lane & 7;
    const int ldr = tid >> 2, ldc = (tid & 3)*8;

    for (int t = blockIdx.x; t < nTiles; t += gridDim.x){
        const int z  = t / tpz;
        const int rr = t - z*tpz;
        const int bm = (rr / tilesN)*128, bn = (rr % tilesN)*64;
        const bf16* __restrict__ aHp = p.aH[z];
        const bf16* __restrict__ aLp = p.aL[z];
        const bf16* __restrict__ wHp = p.wH[z];
        const bf16* __restrict__ wLp = p.wL[z];
        const float* __restrict__ bias = p.bias[z];
        float* Cp = p.C[z];
        bf16* cHp = p.cH[z];
        bf16* cLp = p.cL[z];

        float acc[2][4][4];
        #pragma unroll
        for (int i = 0; i < 2; i++)
            #pragma unroll
            for (int j = 0; j < 4; j++)
                #pragma unroll
                for (int q = 0; q < 4; q++) acc[i][j][q] = 0.f;

        auto loadst = [&](int s, int k0){
            #pragma unroll
            for (int rep = 0; rep < 2; rep++){
                int r = ldr + rep*64;
                int gm = bm + r;
                bool pr = gm < M;
                size_t so = (size_t)(pr ? gm : 0)*K + k0 + ldc;
                unsigned doff = (unsigned)(((s*128 + r)*40 + ldc)*2);
                cp16(aHiB + doff, aHp + so, pr);
                cp16(aLoB + doff, aLp + so, pr);
            }
            {
                int gn = bn + ldr;
                bool pn = gn < N;
                size_t so = (size_t)(pn ? gn : 0)*K + k0 + ldc;
                unsigned doff = (unsigned)(((s*64 + ldr)*40 + ldc)*2);
                cp16(bHiB + doff, wHp + so, pn);
                cp16(bLoB + doff, wLp + so, pn);
            }
            cpcommit();
        };

        loadst(0, 0);
        int buf = 0;
        const int KT = K >> 5;
        for (int kt = 0; kt < KT; kt++){
            if (kt + 1 < KT){ loadst(buf ^ 1, (kt+1)*32); cpwait<1>(); }
            else cpwait<0>();
            __syncthreads();

            #pragma unroll
            for (int kh = 0; kh < 32; kh += 16){
                unsigned ah[2][4], al[2][4], bh[4][2], bl[4][2];
                #pragma unroll
                for (int mt = 0; mt < 2; mt++){
                    int arow = wm + mt*16 + (t4 & 1)*8 + lr;
                    unsigned off = (unsigned)((((buf*128) + arow)*40 + kh + (t4 >> 1)*8)*2);
                    ldsm_x4(ah[mt], aHiB + off);
                    ldsm_x4(al[mt], aLoB + off);
                }
                #pragma unroll
                for (int pr2 = 0; pr2 < 2; pr2++){
                    int brow = wn + pr2*16 + (t4 >> 1)*8 + lr;
                    unsigned off = (unsigned)((((buf*64) + brow)*40 + kh + (t4 & 1)*8)*2);
                    unsigned th[4], tl[4];
                    ldsm_x4(th, bHiB + off);
                    ldsm_x4(tl, bLoB + off);
                    bh[pr2*2][0] = th[0]; bh[pr2*2][1] = th[1];
                    bh[pr2*2+1][0] = th[2]; bh[pr2*2+1][1] = th[3];
                    bl[pr2*2][0] = tl[0]; bl[pr2*2][1] = tl[1];
                    bl[pr2*2+1][0] = tl[2]; bl[pr2*2+1][1] = tl[3];
                }
                #pragma unroll
                for (int mt = 0; mt < 2; mt++)
                    #pragma unroll
                    for (int nt = 0; nt < 4; nt++){
                        mma_bf16(acc[mt][nt], ah[mt], bh[nt]);
                        mma_bf16(acc[mt][nt], ah[mt], bl[nt]);
                        mma_bf16(acc[mt][nt], al[mt], bh[nt]);
                    }
            }
            __syncthreads();
            buf ^= 1;
        }

        #pragma unroll
        for (int mt = 0; mt < 2; mt++)
            #pragma unroll
            for (int nt = 0; nt < 4; nt++){
                int row0 = bm + wm + mt*16 + (lane >> 2);
                int col  = bn + wn + nt*8 + (lane & 3)*2;
                if (col >= N) continue;
                float b0 = bias[col], b1 = bias[col + 1];
                float v0 = acc[mt][nt][0] + b0, v1 = acc[mt][nt][1] + b1;
                float v2 = acc[mt][nt][2] + b0, v3 = acc[mt][nt][3] + b1;
                if (ACT == 1){
                    v0 = gelu_f(v0); v1 = gelu_f(v1);
                    v2 = gelu_f(v2); v3 = gelu_f(v3);
                }
                if (row0 < M){
                    if (Cp){
                        Cp[(size_t)row0*N + col]     = v0;
                        Cp[(size_t)row0*N + col + 1] = v1;
                    }
                    if (cHp){
                        bf16 h0,l0,h1,l1; splitv(v0,h0,l0); splitv(v1,h1,l1);
                        *(__nv_bfloat162*)(cHp + (size_t)row0*N + col) = __halves2bfloat162(h0,h1);
                        *(__nv_bfloat162*)(cLp + (size_t)row0*N + col) = __halves2bfloat162(l0,l1);
                    }
                }
                if (row0 + 8 < M){
                    if (Cp){
                        Cp[(size_t)(row0+8)*N + col]     = v2;
                        Cp[(size_t)(row0+8)*N + col + 1] = v3;
                    }
                    if (cHp){
                        bf16 h2,l2,h3,l3; splitv(v2,h2,l2); splitv(v3,h3,l3);
                        *(__nv_bfloat162*)(cHp + (size_t)(row0+8)*N + col) = __halves2bfloat162(h2,h3);
                        *(__nv_bfloat162*)(cLp + (size_t)(row0+8)*N + col) = __halves2bfloat162(l2,l3);
                    }
                }
            }
    }
}

// =============== flash attention: p_att = softmax(QK^T/sqrt(E)) V =========
// grid (7, B_*NH), 256 threads = 8 warps; warp w owns Q rows i0+w*16..+15.
// smem: K/V hi/lo, 2 stages of 64x40 each; Q staged through same region once.
__global__ __launch_bounds__(256) void flash_attn(){
    __shared__ __align__(16) bf16 sm[20480];   // 40 KB
    const unsigned smB = (unsigned)__cvta_generic_to_shared(sm);
    // byte offsets: KH s*5120 | KL 10240+s*5120 | VH 20480+s*5120 | VL 30720+s*5120
    const int bh = blockIdx.y;
    const int b = bh >> 3, h = bh & 7;
    const int i0 = blockIdx.x * 128;
    const bf16* qH = p_qkv +           (size_t)b*NTOK*D + h*EH;
    const bf16* qL = qH + 3*MD;
    const bf16* kH = p_qkv +    MD +   (size_t)b*NTOK*D + h*EH;
    const bf16* kL = kH + 3*MD;
    const bf16* vH = p_qkv +  2*MD +   (size_t)b*NTOK*D + h*EH;
    const bf16* vL = vH + 3*MD;

    const int tid = threadIdx.x, lane = tid & 31, w = tid >> 5;
    const int t4 = lane >> 3, lr = lane & 7;

    // ---- stage Q through smem, pull into A-fragments ----
    {
        int row = tid >> 1, c = (tid & 1)*16;
        int gi = i0 + row;
        bool ok = gi < NTOK;
        size_t so = (size_t)(ok ? gi : 0)*D + c;
        const float4 z4 = make_float4(0.f,0.f,0.f,0.f);
        float4 f0 = ok ? *(const float4*)(qH + so)     : z4;
        float4 f1 = ok ? *(const float4*)(qH + so + 8) : z4;
        *(float4*)&sm[row*40 + c]     = f0;
        *(float4*)&sm[row*40 + c + 8] = f1;
        f0 = ok ? *(const float4*)(qL + so)     : z4;
        f1 = ok ? *(const float4*)(qL + so + 8) : z4;
        *(float4*)&sm[5120 + row*40 + c]     = f0;
        *(float4*)&sm[5120 + row*40 + c + 8] = f1;
    }
    __syncthreads();
    unsigned qh[2][4], ql[2][4];
    #pragma unroll
    for (int kc = 0; kc < 2; kc++){
        int row = w*16 + (t4 & 1)*8 + lr;
        int col = kc*16 + (t4 >> 1)*8;
        ldsm_x4(qh[kc], smB + (unsigned)((row*40 + col)*2));
        ldsm_x4(ql[kc], smB + (unsigned)((5120 + row*40 + col)*2));
    }
    __syncthreads();

    // ---- K/V tile loader (64 rows x 32 cols, hi/lo, 4 cp16 per thread) ----
    const int ldr = tid >> 2, ldc = (tid & 3)*8;
    auto loadkv = [&](int s, int j0){
        int gj = j0 + ldr;
        bool ok = gj < NTOK;
        size_t so = (size_t)(ok ? gj : 0)*D + ldc;
        unsigned doff = (unsigned)(s*5120 + (ldr*40 + ldc)*2);
        cp16(smB + doff,         kH + so, ok);
        cp16(smB + 10240 + doff, kL + so, ok);
        cp16(smB + 20480 + doff, vH + so, ok);
        cp16(smB + 30720 + doff, vL + so, ok);
        cpcommit();
    };

    float o[4][4];
    #pragma unroll
    for (int j = 0; j < 4; j++)
        #pragma unroll
        for (int q = 0; q < 4; q++) o[j][q] = 0.f;
    float m0 = -1e30f, m1 = -1e30f, l0 = 0.f, l1 = 0.f;
    const float scale = 0.17677669529663688f;  // 1/sqrt(32)

    loadkv(0, 0);
    int buf = 0;
    const int NJT = 14;   // ceil(866/64)
    for (int jt = 0; jt < NJT; jt++){
        const int j0 = jt*64;
        if (jt + 1 < NJT){ loadkv(buf ^ 1, (jt+1)*64); cpwait<1>(); }
        else cpwait<0>();
        __syncthreads();

        // ---- S = Q K^T (128x64 per CTA; 16x64 per warp) ----
        float s[8][4];
        #pragma unroll
        for (int nt = 0; nt < 8; nt++)
            #pragma unroll
            for (int q = 0; q < 4; q++) s[nt][q] = 0.f;

        #pragma unroll
        for (int kc = 0; kc < 2; kc++){
            #pragma unroll
            for (int pr = 0; pr < 4; pr++){
                int brow = pr*16 + (t4 >> 1)*8 + lr;
                int col  = kc*16 + (t4 & 1)*8;
                unsigned off = (unsigned)(buf*5120 + (brow*40 + col)*2);
                unsigned th[4], tl[4];
                ldsm_x4(th, smB + off);
                ldsm_x4(tl, smB + 10240 + off);
                unsigned bh0[2] = {th[0], th[1]}, bh1[2] = {th[2], th[3]};
                unsigned bl0[2] = {tl[0], tl[1]}, bl1[2] = {tl[2], tl[3]};
                mma_bf16(s[2*pr],   qh[kc], bh0);
                mma_bf16(s[2*pr],   qh[kc], bl0);
                mma_bf16(s[2*pr],   ql[kc], bh0);
                mma_bf16(s[2*pr+1], qh[kc], bh1);
                mma_bf16(s[2*pr+1], qh[kc], bl1);
                mma_bf16(s[2*pr+1], ql[kc], bh1);
            }
        }

        // ---- scale + mask ----
        #pragma unroll
        for (int nt = 0; nt < 8; nt++)
            #pragma unroll
            for (int q = 0; q < 4; q++) s[nt][q] *= scale;
        if (j0 + 64 > NTOK){
            #pragma unroll
            for (int nt = 0; nt < 8; nt++){
                int c0 = j0 + nt*8 + (lane & 3)*2;
                if (c0     >= NTOK){ s[nt][0] = -1e30f; s[nt][2] = -1e30f; }
                if (c0 + 1 >= NTOK){ s[nt][1] = -1e30f; s[nt][3] = -1e30f; }
            }
        }

        // ---- online softmax (rows r = lane>>2 and r+8) ----
        float rm0 = -1e30f, rm1 = -1e30f;
        #pragma unroll
        for (int nt = 0; nt < 8; nt++){
            rm0 = fmaxf(rm0, fmaxf(s[nt][0], s[nt][1]));
            rm1 = fmaxf(rm1, fmaxf(s[nt][2], s[nt][3]));
        }
        rm0 = fmaxf(rm0, __shfl_xor_sync(0xffffffffu, rm0, 1));
        rm0 = fmaxf(rm0, __shfl_xor_sync(0xffffffffu, rm0, 2));
        rm1 = fmaxf(rm1, __shfl_xor_sync(0xffffffffu, rm1, 1));
        rm1 = fmaxf(rm1, __shfl_xor_sync(0xffffffffu, rm1, 2));
        float nm0 = fmaxf(m0, rm0), nm1 = fmaxf(m1, rm1);
        float a0 = __expf(m0 - nm0), a1 = __expf(m1 - nm1);
        float ps0 = 0.f, ps1 = 0.f;
        #pragma unroll
        for (int nt = 0; nt < 8; nt++){
            s[nt][0] = __expf(s[nt][0] - nm0);
            s[nt][1] = __expf(s[nt][1] - nm0);
            s[nt][2] = __expf(s[nt][2] - nm1);
            s[nt][3] = __expf(s[nt][3] - nm1);
            ps0 += s[nt][0] + s[nt][1];
            ps1 += s[nt][2] + s[nt][3];
        }
        ps0 += __shfl_xor_sync(0xffffffffu, ps0, 1);
        ps0 += __shfl_xor_sync(0xffffffffu, ps0, 2);
        ps1 += __shfl_xor_sync(0xffffffffu, ps1, 1);
        ps1 += __shfl_xor_sync(0xffffffffu, ps1, 2);
        l0 = l0*a0 + ps0; l1 = l1*a1 + ps1;
        m0 = nm0; m1 = nm1;
        #pragma unroll
        for (int nt = 0; nt < 4; nt++){
            o[nt][0] *= a0; o[nt][1] *= a0;
            o[nt][2] *= a1; o[nt][3] *= a1;
        }

        // ---- O += P V : S C-fragments are P A-fragments in-register ----
        #pragma unroll
        for (int kc2 = 0; kc2 < 4; kc2++){
            unsigned pah[4], pal[4];
            {
                const float* u = s[2*kc2];
                const float* v2 = s[2*kc2 + 1];
                bf16 h0,lo0,h1,lo1;
                splitv(u[0], h0, lo0); splitv(u[1], h1, lo1);
                pah[0] = pack2u(h0, h1);   pal[0] = pack2u(lo0, lo1);
                splitv(u[2], h0, lo0); splitv(u[3], h1, lo1);
                pah[1] = pack2u(h0, h1);   pal[1] = pack2u(lo0, lo1);
                splitv(v2[0], h0, lo0); splitv(v2[1], h1, lo1);
                pah[2] = pack2u(h0, h1);   pal[2] = pack2u(lo0, lo1);
                splitv(v2[2], h0, lo0); splitv(v2[3], h1, lo1);
                pah[3] = pack2u(h0, h1);   pal[3] = pack2u(lo0, lo1);
            }
            #pragma unroll
            for (int pr2 = 0; pr2 < 2; pr2++){
                int krow = kc2*16 + (t4 & 1)*8 + lr;
                int ncol = pr2*16 + (t4 >> 1)*8;
                unsigned off = (unsigned)(buf*5120 + (krow*40 + ncol)*2);
                unsigned th[4], tl[4];
                ldsm_x4t(th, smB + 20480 + off);
                ldsm_x4t(tl, smB + 30720 + off);
                unsigned bh0[2] = {th[0], th[1]}, bh1[2] = {th[2], th[3]};
                unsigned bl0[2] = {tl[0], tl[1]}, bl1[2] = {tl[2], tl[3]};
                mma_bf16(o[2*pr2],   pah, bh0);
                mma_bf16(o[2*pr2],   pah, bl0);
                mma_bf16(o[2*pr2],   pal, bh0);
                mma_bf16(o[2*pr2+1], pah, bh1);
                mma_bf16(o[2*pr2+1], pah, bl1);
                mma_bf16(o[2*pr2+1], pal, bh1);
            }
        }
        __syncthreads();
        buf ^= 1;
    }

    // ---- normalize + write p_att planes ----
    float inv0 = 1.f / l0, inv1 = 1.f / l1;
    #pragma unroll
    for (int nt = 0; nt < 4; nt++){
        int row0 = i0 + w*16 + (lane >> 2);
        int col  = nt*8 + (lane & 3)*2;
        if (row0 < NTOK){
            size_t dst = ((size_t)b*NTOK + row0)*D + h*EH + col;
            bf16 h0,lo0,h1,lo1;
            splitv(o[nt][0]*inv0, h0, lo0); splitv(o[nt][1]*inv0, h1, lo1);
            *(__nv_bfloat162*)(p_att + dst)      = __halves2bfloat162(h0, h1);
            *(__nv_bfloat162*)(p_att + MD + dst) = __halves2bfloat162(lo0, lo1);
        }
        if (row0 + 8 < NTOK){
            size_t dst = ((size_t)b*NTOK + row0 + 8)*D + h*EH + col;
            bf16 h2,lo2,h3,lo3;
            splitv(o[nt][2]*inv1, h2, lo2); splitv(o[nt][3]*inv1, h3, lo3);
            *(__nv_bfloat162*)(p_att + dst)      = __halves2bfloat162(h2, h3);
            *(__nv_bfloat162*)(p_att + MD + dst) = __halves2bfloat162(lo2, lo3);
        }
    }
}

// ---------------- LayerNorm(x [- sub]) over D=256 (+ optional planes) ----
__global__ __launch_bounds__(256) void ln_kernel(const float* __restrict__ X,
                                                 const float* __restrict__ Sub,
                                                 const float* __restrict__ g,
                                                 const float* __restrict__ beta,
                                                 float* __restrict__ Out,
                                                 bf16* __restrict__ pH,
                                                 bf16* __restrict__ pL){
    int row = blockIdx.x, d = threadIdx.x;
    size_t i = (size_t)row*D + d;
    float v = X[i] - (Sub ? Sub[i] : 0.f);
    float mean = blockReduce(v, false) * (1.f/D);
    float dv = v - mean;
    float var = blockReduce(dv*dv, false) * (1.f/D);
    float o = dv * rsqrtf(var + EPS) * g[d] + beta[d];
    Out[i] = o;
    if (pH){
        bf16 hh, ll; splitv(o, hh, ll);
        pH[i] = hh; pL[i] = ll;
    }
}

// ---------------- elementwise ----------------
__global__ void sub_kernel(const float* __restrict__ a, const float* __restrict__ b){
    size_t i = (size_t)blockIdx.x*blockDim.x + threadIdx.x;
    if (i >= MD) return;
    splitv(a[i] - b[i], p_xs[i], p_xs[MD + i]);
}

__global__ void glu_kernel(const float* __restrict__ a, const float* __restrict__ b,
                           float* __restrict__ c, size_t n){
    size_t i = (size_t)blockIdx.x*blockDim.x + threadIdx.x;
    if (i < n) c[i] = (1.f/(1.f + expf(-a[i]))) * b[i];
}

__global__ void cat_kernel(const float* __restrict__ xatt, const float* __restrict__ y){
    size_t i = (size_t)blockIdx.x*blockDim.x + threadIdx.x;
    if (i >= CN) return;
    int c = (int)(i % (2*D));
    size_t r = i / (2*D);
    float v = (c < D) ? xatt[r*D + c] : y[r*D + c - D];
    splitv(v, p_cat[i], p_cat[CN + i]);
}

__global__ void outcomb_kernel(int l){
    size_t n = (size_t)MROWS*DB;
    size_t i = (size_t)blockIdx.x*blockDim.x + threadIdx.x;
    if (i >= n) return;
    float a = g_o56[i], b = g_o56[n + i];
    float v = (1.f/(1.f + expf(-a))) * b;
    g_out[i] = l ? (v - g_out[i]) : v;
}

__global__ void final_kernel(float* __restrict__ out, int t){
    size_t total = (size_t)B_*DB*ENC;
    size_t idx = (size_t)blockIdx.x*blockDim.x + threadIdx.x;
    if (idx >= total) return;
    int n = (int)(idx % ENC);
    size_t r = idx / ENC;
    int p = (int)(r % DB);
    int b = (int)(r / DB);
    float v = g_out[((size_t)b*NTOK + n)*DB + p] * g_std[b*ENC + n] + g_mean[b*ENC + n];
    v *= 0.5f;
    if (t == 0) out[idx] = v; else out[idx] += v;
}

// ---------------- host ----------------
static inline int gsz(int nt){ return nt < 296 ? nt : 296; }
static void* sym(const void* s){ void* p; cudaGetSymbolAddress(&p, s); return p; }

extern "C" void kernel_launch(void* const* d_in, const int* in_sizes, int n_in,
                              void* d_out, int out_size){
    const float* mbx  = (const float*)d_in[0];
    const float* mbxm = (const float*)d_in[1];
    const float* embW = (const float*)d_in[4];
    const float* embB = (const float*)d_in[5];
    const float* Wq = (const float*)d_in[6];
    const float* Wk = (const float*)d_in[7];
    const float* Wv = (const float*)d_in[8];
    const float* Wo = (const float*)d_in[9];
    const float* W3 = (const float*)d_in[10];
    const float* W4 = (const float*)d_in[11];
    const float* bq = (const float*)d_in[12];
    const float* bk = (const float*)d_in[13];
    const float* bv = (const float*)d_in[14];
    const float* bo = (const float*)d_in[15];
    const float* b3 = (const float*)d_in[16];
    const float* b4 = (const float*)d_in[17];
    const float* W1 = (const float*)d_in[18];
    const float* b1 = (const float*)d_in[19];
    const float* W2 = (const float*)d_in[20];
    const float* b2 = (const float*)d_in[21];
    const float* W5 = (const float*)d_in[22];
    const float* b5 = (const float*)d_in[23];
    const float* W6 = (const float*)d_in[24];
    const float* b6 = (const float*)d_in[25];
    const float* ln1g = (const float*)d_in[26];
    const float* ln1b = (const float*)d_in[27];
    const float* ln2g = (const float*)d_in[28];
    const float* ln2b = (const float*)d_in[29];
    float* out = (float*)d_out;

    float* hF   = (float*)sym(g_h);
    float* xatt = (float*)sym(g_xatt);
    float* xln  = (float*)sym(g_xln);
    float* yF   = (float*)sym(g_y);
    float* hhF  = (float*)sym(g_hh);
    float* g34F = (float*)sym(g_g34);
    float* o56F = (float*)sym(g_o56);

    bf16* xinP = (bf16*)sym(p_xin);
    bf16* hP   = (bf16*)sym(p_h);
    bf16* qkvP = (bf16*)sym(p_qkv);
    bf16* attP = (bf16*)sym(p_att);
    bf16* xlnP = (bf16*)sym(p_xln);
    bf16* y1P  = (bf16*)sym(p_y1);
    bf16* xsP  = (bf16*)sym(p_xs);
    bf16* catP = (bf16*)sym(p_cat);
    bf16* embWP = (bf16*)sym(p_embW);
    bf16* WqP = (bf16*)sym(p_Wq); bf16* WkP = (bf16*)sym(p_Wk);
    bf16* WvP = (bf16*)sym(p_Wv); bf16* WoP = (bf16*)sym(p_Wo);
    bf16* W3P = (bf16*)sym(p_W3); bf16* W4P = (bf16*)sym(p_W4);
    bf16* W1P = (bf16*)sym(p_W1); bf16* W2P = (bf16*)sym(p_W2);
    bf16* W5P = (bf16*)sym(p_W5); bf16* W6P = (bf16*)sym(p_W6);

    const size_t XN  = (size_t)MROWS*SEQP;
    const size_t EWN = (size_t)256*SEQP;
    const size_t WDD = (size_t)LAYERS*D*D;
    const size_t W1N = (size_t)LAYERS*DFF*D;
    const size_t W5N = (size_t)LAYERS*DB*2*D;
    const size_t Y1N = (size_t)MROWS*DFF;

    cudaFuncSetAttribute(mma_gemm<0>, cudaFuncAttributeMaxDynamicSharedMemorySize, 61440);
    cudaFuncSetAttribute(mma_gemm<1>, cudaFuncAttributeMaxDynamicSharedMemorySize, 61440);

    // weight splits (once per call)
    wsplit_pad<<<(unsigned)((EWN + 255)/256), 256>>>(embW, embWP, embWP + EWN, 256, SEQ, SEQP);
    wsplit<<<(unsigned)((WDD + 255)/256), 256>>>(Wq, WqP, WqP + WDD, WDD);
    wsplit<<<(unsigned)((WDD + 255)/256), 256>>>(Wk, WkP, WkP + WDD, WDD);
    wsplit<<<(unsigned)((WDD + 255)/256), 256>>>(Wv, WvP, WvP + WDD, WDD);
    wsplit<<<(unsigned)((WDD + 255)/256), 256>>>(Wo, WoP, WoP + WDD, WDD);
    wsplit<<<(unsigned)((WDD + 255)/256), 256>>>(W3, W3P, W3P + WDD, WDD);
    wsplit<<<(unsigned)((WDD + 255)/256), 256>>>(W4, W4P, W4P + WDD, WDD);
    wsplit<<<(unsigned)((W1N + 255)/256), 256>>>(W1, W1P, W1P + W1N, W1N);
    wsplit<<<(unsigned)((W1N + 255)/256), 256>>>(W2, W2P, W2P + W1N, W1N);
    wsplit<<<(unsigned)((W5N + 255)/256), 256>>>(W5, W5P, W5P + W5N, W5N);
    wsplit<<<(unsigned)((W5N + 255)/256), 256>>>(W6, W6P, W6P + W5N, W5N);

    const int tm = 55;  // ceil(6928/128)

    for (int t = 0; t < TS; t++){
        stats_kernel<<<dim3((ENC + 255)/256, B_), 256>>>(mbx, t);
        xin_kernel<<<(unsigned)((XN + 255)/256), 256>>>(mbx, mbxm, t);

        {   // embed: M=6928, N=256, K=736 -> fp32 h + planes
            GemmArgs a = {};
            a.aH[0] = xinP; a.aL[0] = xinP + XN;
            a.wH[0] = embWP; a.wL[0] = embWP + EWN;
            a.bias[0] = embB; a.C[0] = hF;
            a.cH[0] = hP; a.cL[0] = hP + MD;
            mma_gemm<0><<<gsz(tm*4), 256, 61440>>>(a, MROWS, D, SEQP, 4, tm*4, tm*4);
        }

        for (int l = 0; l < LAYERS; l++){
            {   // QKV -> planes only
                GemmArgs a = {};
                for (int z = 0; z < 3; z++){
                    a.aH[z] = hP; a.aL[z] = hP + MD;
                    a.cH[z] = qkvP + (size_t)z*MD;
                    a.cL[z] = qkvP + 3*MD + (size_t)z*MD;
                }
                a.wH[0] = WqP + (size_t)l*D*D; a.wL[0] = WqP + WDD + (size_t)l*D*D;
                a.wH[1] = WkP + (size_t)l*D*D; a.wL[1] = WkP + WDD + (size_t)l*D*D;
                a.wH[2] = WvP + (size_t)l*D*D; a.wL[2] = WvP + WDD + (size_t)l*D*D;
                a.bias[0] = bq + l*D; a.bias[1] = bk + l*D; a.bias[2] = bv + l*D;
                mma_gemm<0><<<gsz(tm*4*3), 256, 61440>>>(a, MROWS, D, D, 4, tm*4, tm*4*3);
            }

            flash_attn<<<dim3(7, B_*NH), 256>>>();

            {   // Wo: att planes -> fp32 xatt
                GemmArgs a = {};
                a.aH[0] = attP; a.aL[0] = attP + MD;
                a.wH[0] = WoP + (size_t)l*D*D; a.wL[0] = WoP + WDD + (size_t)l*D*D;
                a.bias[0] = bo + l*D; a.C[0] = xatt;
                mma_gemm<0><<<gsz(tm*4), 256, 61440>>>(a, MROWS, D, D, 4, tm*4, tm*4);
            }

            ln_kernel<<<MROWS, 256>>>(hF, xatt, ln1g + l*D, ln1b + l*D, xln,
                                      xlnP, xlnP + MD);

            {   // W1 + GELU -> y1 planes only
                GemmArgs a = {};
                a.aH[0] = xlnP; a.aL[0] = xlnP + MD;
                a.wH[0] = W1P + (size_t)l*DFF*D; a.wL[0] = W1P + W1N + (size_t)l*DFF*D;
                a.bias[0] = b1 + l*DFF;
                a.cH[0] = y1P; a.cL[0] = y1P + Y1N;
                mma_gemm<1><<<gsz(tm*8), 256, 61440>>>(a, MROWS, DFF, D, 8, tm*8, tm*8);
            }
            {   // W2 -> fp32 y
                GemmArgs a = {};
                a.aH[0] = y1P; a.aL[0] = y1P + Y1N;
                a.wH[0] = W2P + (size_t)l*D*DFF; a.wL[0] = W2P + W1N + (size_t)l*D*DFF;
                a.bias[0] = b2 + l*D; a.C[0] = yF;
                mma_gemm<0><<<gsz(tm*4), 256, 61440>>>(a, MROWS, D, DFF, 4, tm*4, tm*4);
            }

            sub_kernel<<<(unsigned)((MD + 255)/256), 256>>>(xln, yF);

            {   // W3/W4 -> fp32 pair in g_g34
                GemmArgs a = {};
                for (int z = 0; z < 2; z++){
                    a.aH[z] = xsP; a.aL[z] = xsP + MD;
                    a.C[z] = g34F + (size_t)z*MD;
                }
                a.wH[0] = W3P + (size_t)l*D*D; a.wL[0] = W3P + WDD + (size_t)l*D*D;
                a.wH[1] = W4P + (size_t)l*D*D; a.wL[1] = W4P + WDD + (size_t)l*D*D;
                a.bias[0] = b3 + l*D; a.bias[1] = b4 + l*D;
                mma_gemm<0><<<gsz(tm*4*2), 256, 61440>>>(a, MROWS, D, D, 4, tm*4, tm*4*2);
            }

            glu_kernel<<<(unsigned)((MD + 255)/256), 256>>>(g34F, g34F + MD, hhF, MD);
            cat_kernel<<<(unsigned)((CN + 255)/256), 256>>>(xatt, yF);

            {   // W5/W6 -> fp32 pair in g_o56
                GemmArgs a = {};
                for (int z = 0; z < 2; z++){
                    a.aH[z] = catP; a.aL[z] = catP + CN;
                    a.C[z] = o56F + (size_t)z*MROWS*DB;
                }
                a.wH[0] = W5P + (size_t)l*DB*2*D; a.wL[0] = W5P + W5N + (size_t)l*DB*2*D;
                a.wH[1] = W6P + (size_t)l*DB*2*D; a.wL[1] = W6P + W5N + (size_t)l*DB*2*D;
                a.bias[0] = b5 + l*DB; a.bias[1] = b6 + l*DB;
                mma_gemm<0><<<gsz(tm*12*2), 256, 61440>>>(a, MROWS, DB, 2*D, 12, tm*12, tm*12*2);
            }

            outcomb_kernel<<<(unsigned)(((size_t)MROWS*DB + 255)/256), 256>>>(l);

            ln_kernel<<<MROWS, 256>>>(hhF, (const float*)nullptr,
                                      ln2g + l*D, ln2b + l*D, hF, hP, hP + MD);
        }

        final_kernel<<<(unsigned)(((size_t)B_*DB*ENC + 255)/256), 256>>>(out, t);
    }
}

// round 8
// speedup vs baseline: 4.4103x; 1.0784x over previous
#include <cuda_runtime.h>
#include <cuda_bf16.h>
#include <math.h>

#define B_    8
#define TS    2
#define SEQ   720
#define SEQP  736
#define ENC   862
#define MARKD 4
#define NTOK  866
#define D     256
#define NH    8
#define EH    32
#define DFF   512
#define DB    720
#define LAYERS 2
#define EPS   1e-5f
#define MROWS (B_*NTOK)   // 6928
#define MD    ((size_t)MROWS*D)

typedef __nv_bfloat16 bf16;

// ---------------- fp32 scratch ----------------
__device__ float g_mean[B_*ENC], g_std[B_*ENC];
__device__ float g_h[MD], g_xatt[MD], g_xln[MD], g_hh[MD];
__device__ float g_out[(size_t)MROWS*DB];

// ---------------- bf16 hi/lo planes (lo at +n) ----------------
__device__ __align__(16) bf16 p_xin[2*(size_t)MROWS*SEQP];
__device__ __align__(16) bf16 p_h  [2*MD];
__device__ __align__(16) bf16 p_qkv[2*3*MD];
__device__ __align__(16) bf16 p_att[2*MD];
__device__ __align__(16) bf16 p_xln[2*MD];
__device__ __align__(16) bf16 p_y1 [2*(size_t)MROWS*DFF];
__device__ __align__(16) bf16 p_xs [2*MD];
__device__ __align__(16) bf16 p_xatt[2*MD];
__device__ __align__(16) bf16 p_y  [2*MD];
// weights
__device__ __align__(16) bf16 p_embW[2*256*SEQP];
__device__ __align__(16) bf16 p_Wq[2*LAYERS*D*D], p_Wk[2*LAYERS*D*D], p_Wv[2*LAYERS*D*D];
__device__ __align__(16) bf16 p_Wo[2*LAYERS*D*D], p_W3[2*LAYERS*D*D], p_W4[2*LAYERS*D*D];
__device__ __align__(16) bf16 p_W1[2*LAYERS*DFF*D], p_W2[2*LAYERS*D*DFF];
__device__ __align__(16) bf16 p_W5[2*LAYERS*DB*2*D], p_W6[2*LAYERS*DB*2*D];

// ---------------- helpers ----------------
__device__ __forceinline__ void splitv(float x, bf16& h, bf16& l){
    h = __float2bfloat16(x);
    l = __float2bfloat16(x - __bfloat162float(h));
}
__device__ __forceinline__ unsigned pack2u(bf16 a, bf16 b){
    __nv_bfloat162 t = __halves2bfloat162(a, b);
    return *(unsigned*)&t;
}
__device__ __forceinline__ void mma_bf16(float c[4], const unsigned a[4], const unsigned b[2]){
    asm volatile("mma.sync.aligned.m16n8k16.row.col.f32.bf16.bf16.f32 "
                 "{%0,%1,%2,%3}, {%4,%5,%6,%7}, {%8,%9}, {%0,%1,%2,%3};\n"
                 : "+f"(c[0]), "+f"(c[1]), "+f"(c[2]), "+f"(c[3])
                 : "r"(a[0]), "r"(a[1]), "r"(a[2]), "r"(a[3]),
                   "r"(b[0]), "r"(b[1]));
}
__device__ __forceinline__ void ldsm_x4(unsigned r[4], unsigned addr){
    asm volatile("ldmatrix.sync.aligned.m8n8.x4.shared.b16 {%0,%1,%2,%3}, [%4];\n"
                 : "=r"(r[0]), "=r"(r[1]), "=r"(r[2]), "=r"(r[3]) : "r"(addr));
}
__device__ __forceinline__ void ldsm_x4t(unsigned r[4], unsigned addr){
    asm volatile("ldmatrix.sync.aligned.m8n8.x4.trans.shared.b16 {%0,%1,%2,%3}, [%4];\n"
                 : "=r"(r[0]), "=r"(r[1]), "=r"(r[2]), "=r"(r[3]) : "r"(addr));
}
__device__ __forceinline__ void cp16(unsigned dst, const void* src, bool p){
    int sz = p ? 16 : 0;
    asm volatile("cp.async.cg.shared.global [%0], [%1], 16, %2;\n"
                 :: "r"(dst), "l"(src), "r"(sz));
}
__device__ __forceinline__ void cpcommit(){ asm volatile("cp.async.commit_group;\n"); }
template<int N> __device__ __forceinline__ void cpwait(){
    asm volatile("cp.async.wait_group %0;\n" :: "n"(N));
}
__device__ __forceinline__ float gelu_f(float x){
    return 0.5f*x*(1.f + erff(x*0.70710678118654752f));
}
__device__ __forceinline__ float sigmoid_f(float x){
    return 1.f/(1.f + expf(-x));
}
__device__ __forceinline__ float blockReduce(float v, bool domax){
    __shared__ float sh[33];
    int lane = threadIdx.x & 31, wid = threadIdx.x >> 5;
    __syncthreads();
    #pragma unroll
    for (int o = 16; o; o >>= 1){
        float ov = __shfl_down_sync(0xffffffffu, v, o);
        v = domax ? fmaxf(v, ov) : (v + ov);
    }
    if (lane == 0) sh[wid] = v;
    __syncthreads();
    if (wid == 0){
        int nw = blockDim.x >> 5;
        v = (lane < nw) ? sh[lane] : (domax ? -1e30f : 0.f);
        #pragma unroll
        for (int o = 16; o; o >>= 1){
            float ov = __shfl_down_sync(0xffffffffu, v, o);
            v = domax ? fmaxf(v, ov) : (v + ov);
        }
        if (lane == 0) sh[32] = v;
    }
    __syncthreads();
    return sh[32];
}

// ---------------- weight split (batched) ----------------
struct WSArgs { const float* s[10]; bf16* h[10]; bf16* l[10]; int n[10]; };
__global__ void wsplit_all(WSArgs w){
    int z = blockIdx.y;
    int n = w.n[z];
    const float* src = w.s[z];
    bf16* hh = w.h[z]; bf16* ll = w.l[z];
    for (int i = blockIdx.x*blockDim.x + threadIdx.x; i < n; i += gridDim.x*blockDim.x)
        splitv(src[i], hh[i], ll[i]);
}
__global__ void wsplit_pad(const float* __restrict__ s, bf16* __restrict__ h,
                           bf16* __restrict__ l, int rows, int K, int Kp){
    size_t i = (size_t)blockIdx.x*blockDim.x + threadIdx.x;
    size_t total = (size_t)rows*Kp;
    if (i >= total) return;
    int c = (int)(i % Kp); int r = (int)(i / Kp);
    float v = (c < K) ? s[(size_t)r*K + c] : 0.f;
    splitv(v, h[i], l[i]);
}

// ---------------- input standardization ----------------
__global__ void stats_kernel(const float* __restrict__ mbx, int t){
    int b = blockIdx.y;
    int n = blockIdx.x * blockDim.x + threadIdx.x;
    if (n >= ENC) return;
    const float* base = mbx + ((size_t)(b*TS + t)*SEQ)*ENC + n;
    float s = 0.f, ss = 0.f;
    for (int i = 0; i < SEQ; i++){
        float v = base[(size_t)i*ENC];
        s += v; ss += v*v;
    }
    float m = s * (1.f/SEQ);
    float var = ss * (1.f/SEQ) - m*m;
    g_mean[b*ENC + n] = m;
    g_std [b*ENC + n] = sqrtf(var + EPS);
}

__global__ void xin_kernel(const float* __restrict__ mbx,
                           const float* __restrict__ mbxm, int t){
    size_t total = (size_t)MROWS*SEQP;
    size_t idx = (size_t)blockIdx.x*blockDim.x + threadIdx.x;
    if (idx >= total) return;
    int s = (int)(idx % SEQP);
    size_t r = idx / SEQP;
    int n = (int)(r % NTOK);
    int b = (int)(r / NTOK);
    float v = 0.f;
    if (s < SEQ){
        if (n < ENC){
            v = mbx[((size_t)(b*TS + t)*SEQ + s)*ENC + n];
            v = (v - g_mean[b*ENC + n]) / g_std[b*ENC + n];
        } else {
            v = mbxm[((size_t)(b*TS + t)*SEQ + s)*MARKD + (n - ENC)];
        }
    }
    splitv(v, p_xin[idx], p_xin[total + idx]);
}

// =============== MMA GEMM: C = A @ W^T + bias (bf16 planes, cp.async) =====
// ACT 0: plain; 1: gelu; 2: emit y planes + (xsub - y) planes
struct GemmArgs {
    const bf16 *aH[3], *aL[3], *wH[3], *wL[3];
    const float* bias[3];
    float* C[3];
    bf16 *cH[3], *cL[3];
    const float* xsub[3];
    bf16 *c2H[3], *c2L[3];
};

template<int ACT>
__global__ __launch_bounds__(256)
void mma_gemm(GemmArgs p, int M, int N, int K, int tilesN, int tpz, int nTiles){
    extern __shared__ __align__(16) char smraw[];
    bf16* sAh = (bf16*)smraw;            // [2][128][40]
    bf16* sAl = sAh + 2*128*40;
    bf16* sBh = sAl + 2*128*40;          // [2][64][40]
    bf16* sBl = sBh + 2*64*40;
    const unsigned aHiB = (unsigned)__cvta_generic_to_shared(sAh);
    const unsigned aLoB = (unsigned)__cvta_generic_to_shared(sAl);
    const unsigned bHiB = (unsigned)__cvta_generic_to_shared(sBh);
    const unsigned bLoB = (unsigned)__cvta_generic_to_shared(sBl);

    const int tid = threadIdx.x;
    const int lane = tid & 31, w = tid >> 5;
    const int wm = (w >> 1)*32, wn = (w & 1)*32;
    const int t4 = lane >> 3, lr = lane & 7;
    const int ldr = tid >> 2, ldc = (tid & 3)*8;

    for (int t = blockIdx.x; t < nTiles; t += gridDim.x){
        const int z  = t / tpz;
        const int rr = t - z*tpz;
        const int bm = (rr / tilesN)*128, bn = (rr % tilesN)*64;
        const bf16* __restrict__ aHp = p.aH[z];
        const bf16* __restrict__ aLp = p.aL[z];
        const bf16* __restrict__ wHp = p.wH[z];
        const bf16* __restrict__ wLp = p.wL[z];
        const float* __restrict__ bias = p.bias[z];
        float* Cp = p.C[z];
        bf16* cHp = p.cH[z];
        bf16* cLp = p.cL[z];

        float acc[2][4][4];
        #pragma unroll
        for (int i = 0; i < 2; i++)
            #pragma unroll
            for (int j = 0; j < 4; j++)
                #pragma unroll
                for (int q = 0; q < 4; q++) acc[i][j][q] = 0.f;

        auto loadst = [&](int s, int k0){
            #pragma unroll
            for (int rep = 0; rep < 2; rep++){
                int r = ldr + rep*64;
                int gm = bm + r;
                bool pr = gm < M;
                size_t so = (size_t)(pr ? gm : 0)*K + k0 + ldc;
                unsigned doff = (unsigned)(((s*128 + r)*40 + ldc)*2);
                cp16(aHiB + doff, aHp + so, pr);
                cp16(aLoB + doff, aLp + so, pr);
            }
            {
                int gn = bn + ldr;
                bool pn = gn < N;
                size_t so = (size_t)(pn ? gn : 0)*K + k0 + ldc;
                unsigned doff = (unsigned)(((s*64 + ldr)*40 + ldc)*2);
                cp16(bHiB + doff, wHp + so, pn);
                cp16(bLoB + doff, wLp + so, pn);
            }
            cpcommit();
        };

        loadst(0, 0);
        int buf = 0;
        const int KT = K >> 5;
        for (int kt = 0; kt < KT; kt++){
            if (kt + 1 < KT){ loadst(buf ^ 1, (kt+1)*32); cpwait<1>(); }
            else cpwait<0>();
            __syncthreads();

            #pragma unroll
            for (int kh = 0; kh < 32; kh += 16){
                unsigned ah[2][4], al[2][4], bh[4][2], bl[4][2];
                #pragma unroll
                for (int mt = 0; mt < 2; mt++){
                    int arow = wm + mt*16 + (t4 & 1)*8 + lr;
                    unsigned off = (unsigned)((((buf*128) + arow)*40 + kh + (t4 >> 1)*8)*2);
                    ldsm_x4(ah[mt], aHiB + off);
                    ldsm_x4(al[mt], aLoB + off);
                }
                #pragma unroll
                for (int pr2 = 0; pr2 < 2; pr2++){
                    int brow = wn + pr2*16 + (t4 >> 1)*8 + lr;
                    unsigned off = (unsigned)((((buf*64) + brow)*40 + kh + (t4 & 1)*8)*2);
                    unsigned th[4], tl[4];
                    ldsm_x4(th, bHiB + off);
                    ldsm_x4(tl, bLoB + off);
                    bh[pr2*2][0] = th[0]; bh[pr2*2][1] = th[1];
                    bh[pr2*2+1][0] = th[2]; bh[pr2*2+1][1] = th[3];
                    bl[pr2*2][0] = tl[0]; bl[pr2*2][1] = tl[1];
                    bl[pr2*2+1][0] = tl[2]; bl[pr2*2+1][1] = tl[3];
                }
                #pragma unroll
                for (int mt = 0; mt < 2; mt++)
                    #pragma unroll
                    for (int nt = 0; nt < 4; nt++){
                        mma_bf16(acc[mt][nt], ah[mt], bh[nt]);
                        mma_bf16(acc[mt][nt], ah[mt], bl[nt]);
                        mma_bf16(acc[mt][nt], al[mt], bh[nt]);
                    }
            }
            __syncthreads();
            buf ^= 1;
        }

        #pragma unroll
        for (int mt = 0; mt < 2; mt++)
            #pragma unroll
            for (int nt = 0; nt < 4; nt++){
                int row0 = bm + wm + mt*16 + (lane >> 2);
                int col  = bn + wn + nt*8 + (lane & 3)*2;
                if (col >= N) continue;
                float b0 = bias[col], b1 = bias[col + 1];
                float v0 = acc[mt][nt][0] + b0, v1 = acc[mt][nt][1] + b1;
                float v2 = acc[mt][nt][2] + b0, v3 = acc[mt][nt][3] + b1;
                if (ACT == 1){
                    v0 = gelu_f(v0); v1 = gelu_f(v1);
                    v2 = gelu_f(v2); v3 = gelu_f(v3);
                }
                if (row0 < M){
                    size_t ix = (size_t)row0*N + col;
                    if (Cp){ Cp[ix] = v0; Cp[ix + 1] = v1; }
                    if (cHp){
                        bf16 h0,l0,h1,l1; splitv(v0,h0,l0); splitv(v1,h1,l1);
                        *(__nv_bfloat162*)(cHp + ix) = __halves2bfloat162(h0,h1);
                        *(__nv_bfloat162*)(cLp + ix) = __halves2bfloat162(l0,l1);
                    }
                    if (ACT == 2){
                        float x0 = p.xsub[z][ix], x1 = p.xsub[z][ix + 1];
                        bf16 h0,l0,h1,l1; splitv(x0 - v0,h0,l0); splitv(x1 - v1,h1,l1);
                        *(__nv_bfloat162*)(p.c2H[z] + ix) = __halves2bfloat162(h0,h1);
                        *(__nv_bfloat162*)(p.c2L[z] + ix) = __halves2bfloat162(l0,l1);
                    }
                }
                if (row0 + 8 < M){
                    size_t ix = (size_t)(row0+8)*N + col;
                    if (Cp){ Cp[ix] = v2; Cp[ix + 1] = v3; }
                    if (cHp){
                        bf16 h2,l2,h3,l3; splitv(v2,h2,l2); splitv(v3,h3,l3);
                        *(__nv_bfloat162*)(cHp + ix) = __halves2bfloat162(h2,h3);
                        *(__nv_bfloat162*)(cLp + ix) = __halves2bfloat162(l2,l3);
                    }
                    if (ACT == 2){
                        float x2 = p.xsub[z][ix], x3 = p.xsub[z][ix + 1];
                        bf16 h2,l2,h3,l3; splitv(x2 - v2,h2,l2); splitv(x3 - v3,h3,l3);
                        *(__nv_bfloat162*)(p.c2H[z] + ix) = __halves2bfloat162(h2,h3);
                        *(__nv_bfloat162*)(p.c2L[z] + ix) = __halves2bfloat162(l2,l3);
                    }
                }
            }
    }
}

// =============== fused dual GEMM: o = sigmoid(A W1^T + b1)*(A W2^T + b2) ===
// BM=64, BN=64, BK=32; A source switches at kSplit (concat fusion).
// MODE 0: Cout = o ;  MODE 1: Cout = sub ? (o - Cout) : o
struct Gemm2Args {
    const bf16 *a0H, *a0L, *a1H, *a1L;
    int kSplit, aStride;
    const bf16 *w1H, *w1L, *w2H, *w2L;
    const float *b1, *b2;
    float* Cout;
    int sub;
};

template<int MODE>
__global__ __launch_bounds__(256)
void mma_gemm2(Gemm2Args p, int M, int N, int K, int tilesN, int nTiles){
    extern __shared__ __align__(16) char smraw[];
    bf16* sm = (bf16*)smraw;
    const unsigned smB = (unsigned)__cvta_generic_to_shared(sm);
    // elements: A(stage s, plane q): (s*2+q)*2560 ; B base 10240 + ((s*4)+(g*2)+q)*2560
    const int tid = threadIdx.x;
    const int lane = tid & 31, w = tid >> 5;
    const int wm = (w >> 1)*16, wn = (w & 1)*32;
    const int t4 = lane >> 3, lr = lane & 7;
    const int ldr = tid >> 2, ldc = (tid & 3)*8;

    for (int t = blockIdx.x; t < nTiles; t += gridDim.x){
        const int bm = (t / tilesN)*64, bn = (t % tilesN)*64;

        float acc[2][4][4];
        #pragma unroll
        for (int g = 0; g < 2; g++)
            #pragma unroll
            for (int j = 0; j < 4; j++)
                #pragma unroll
                for (int q = 0; q < 4; q++) acc[g][j][q] = 0.f;

        auto loadst = [&](int s, int k0){
            const bf16* aH = (k0 < p.kSplit) ? p.a0H : p.a1H;
            const bf16* aL = (k0 < p.kSplit) ? p.a0L : p.a1L;
            int kk = (k0 < p.kSplit) ? k0 : k0 - p.kSplit;
            {
                int gm = bm + ldr;
                bool pr = gm < M;
                size_t so = (size_t)(pr ? gm : 0)*p.aStride + kk + ldc;
                unsigned d0 = (unsigned)(((s*2 + 0)*2560 + ldr*40 + ldc)*2);
                unsigned d1 = (unsigned)(((s*2 + 1)*2560 + ldr*40 + ldc)*2);
                cp16(smB + d0, aH + so, pr);
                cp16(smB + d1, aL + so, pr);
            }
            {
                int gn = bn + ldr;
                bool pn = gn < N;
                size_t so = (size_t)(pn ? gn : 0)*K + k0 + ldc;
                unsigned base = 10240u;
                unsigned doff = (unsigned)((ldr*40 + ldc)*2);
                cp16(smB + (base + (s*4 + 0)*2560)*2 - base*2 + base*2 + doff, p.w1H + so, pn);
                // (written explicitly below instead)
            }
            cpcommit();
        };
        (void)loadst;

        // explicit loader (clearer offsets)
        auto loadst2 = [&](int s, int k0){
            const bf16* aH = (k0 < p.kSplit) ? p.a0H : p.a1H;
            const bf16* aL = (k0 < p.kSplit) ? p.a0L : p.a1L;
            int kk = (k0 < p.kSplit) ? k0 : k0 - p.kSplit;
            int gm = bm + ldr;
            bool pr = gm < M;
            size_t soA = (size_t)(pr ? gm : 0)*p.aStride + kk + ldc;
            unsigned dA = (unsigned)((s*2*2560 + ldr*40 + ldc)*2);
            cp16(smB + dA,           aH + soA, pr);
            cp16(smB + dA + 2560*2,  aL + soA, pr);
            int gn = bn + ldr;
            bool pn = gn < N;
            size_t soB = (size_t)(pn ? gn : 0)*K + k0 + ldc;
            unsigned dB = (unsigned)((10240 + s*4*2560 + ldr*40 + ldc)*2);
            cp16(smB + dB,             p.w1H + soB, pn);
            cp16(smB + dB + 2560*2,    p.w1L + soB, pn);
            cp16(smB + dB + 2*2560*2,  p.w2H + soB, pn);
            cp16(smB + dB + 3*2560*2,  p.w2L + soB, pn);
            cpcommit();
        };

        loadst2(0, 0);
        int buf = 0;
        const int KT = K >> 5;
        for (int kt = 0; kt < KT; kt++){
            if (kt + 1 < KT){ loadst2(buf ^ 1, (kt+1)*32); cpwait<1>(); }
            else cpwait<0>();
            __syncthreads();

            #pragma unroll
            for (int kh = 0; kh < 32; kh += 16){
                unsigned ah[4], al[4];
                {
                    int arow = wm + (t4 & 1)*8 + lr;
                    unsigned off = (unsigned)((buf*2*2560 + arow*40 + kh + (t4 >> 1)*8)*2);
                    ldsm_x4(ah, smB + off);
                    ldsm_x4(al, smB + off + 2560*2);
                }
                #pragma unroll
                for (int g = 0; g < 2; g++){
                    #pragma unroll
                    for (int pr2 = 0; pr2 < 2; pr2++){
                        int brow = wn + pr2*16 + (t4 >> 1)*8 + lr;
                        unsigned off = (unsigned)((10240 + buf*4*2560 + g*2*2560
                                                   + brow*40 + kh + (t4 & 1)*8)*2);
                        unsigned th[4], tl[4];
                        ldsm_x4(th, smB + off);
                        ldsm_x4(tl, smB + off + 2560*2);
                        unsigned bh0[2] = {th[0], th[1]}, bh1[2] = {th[2], th[3]};
                        unsigned bl0[2] = {tl[0], tl[1]}, bl1[2] = {tl[2], tl[3]};
                        mma_bf16(acc[g][2*pr2],   ah, bh0);
                        mma_bf16(acc[g][2*pr2],   ah, bl0);
                        mma_bf16(acc[g][2*pr2],   al, bh0);
                        mma_bf16(acc[g][2*pr2+1], ah, bh1);
                        mma_bf16(acc[g][2*pr2+1], ah, bl1);
                        mma_bf16(acc[g][2*pr2+1], al, bh1);
                    }
                }
            }
            __syncthreads();
            buf ^= 1;
        }

        #pragma unroll
        for (int nt = 0; nt < 4; nt++){
            int row0 = bm + wm + (lane >> 2);
            int col  = bn + wn + nt*8 + (lane & 3)*2;
            if (col >= N) continue;
            float b10 = p.b1[col], b11 = p.b1[col + 1];
            float b20 = p.b2[col], b21 = p.b2[col + 1];
            float o0 = sigmoid_f(acc[0][nt][0] + b10)*(acc[1][nt][0] + b20);
            float o1 = sigmoid_f(acc[0][nt][1] + b11)*(acc[1][nt][1] + b21);
            float o2 = sigmoid_f(acc[0][nt][2] + b10)*(acc[1][nt][2] + b20);
            float o3 = sigmoid_f(acc[0][nt][3] + b11)*(acc[1][nt][3] + b21);
            if (row0 < M){
                size_t ix = (size_t)row0*N + col;
                if (MODE == 1 && p.sub){
                    p.Cout[ix]     = o0 - p.Cout[ix];
                    p.Cout[ix + 1] = o1 - p.Cout[ix + 1];
                } else {
                    p.Cout[ix] = o0; p.Cout[ix + 1] = o1;
                }
            }
            if (row0 + 8 < M){
                size_t ix = (size_t)(row0+8)*N + col;
                if (MODE == 1 && p.sub){
                    p.Cout[ix]     = o2 - p.Cout[ix];
                    p.Cout[ix + 1] = o3 - p.Cout[ix + 1];
                } else {
                    p.Cout[ix] = o2; p.Cout[ix + 1] = o3;
                }
            }
        }
    }
}

// =============== flash attention ==========================================
__global__ __launch_bounds__(256) void flash_attn(){
    __shared__ __align__(16) bf16 sm[20480];   // 40 KB
    const unsigned smB = (unsigned)__cvta_generic_to_shared(sm);
    const int bh = blockIdx.y;
    const int b = bh >> 3, h = bh & 7;
    const int i0 = blockIdx.x * 128;
    const bf16* qH = p_qkv +           (size_t)b*NTOK*D + h*EH;
    const bf16* qL = qH + 3*MD;
    const bf16* kH = p_qkv +    MD +   (size_t)b*NTOK*D + h*EH;
    const bf16* kL = kH + 3*MD;
    const bf16* vH = p_qkv +  2*MD +   (size_t)b*NTOK*D + h*EH;
    const bf16* vL = vH + 3*MD;

    const int tid = threadIdx.x, lane = tid & 31, w = tid >> 5;
    const int t4 = lane >> 3, lr = lane & 7;

    {
        int row = tid >> 1, c = (tid & 1)*16;
        int gi = i0 + row;
        bool ok = gi < NTOK;
        size_t so = (size_t)(ok ? gi : 0)*D + c;
        const float4 z4 = make_float4(0.f,0.f,0.f,0.f);
        float4 f0 = ok ? *(const float4*)(qH + so)     : z4;
        float4 f1 = ok ? *(const float4*)(qH + so + 8) : z4;
        *(float4*)&sm[row*40 + c]     = f0;
        *(float4*)&sm[row*40 + c + 8] = f1;
        f0 = ok ? *(const float4*)(qL + so)     : z4;
        f1 = ok ? *(const float4*)(qL + so + 8) : z4;
        *(float4*)&sm[5120 + row*40 + c]     = f0;
        *(float4*)&sm[5120 + row*40 + c + 8] = f1;
    }
    __syncthreads();
    unsigned qh[2][4], ql[2][4];
    #pragma unroll
    for (int kc = 0; kc < 2; kc++){
        int row = w*16 + (t4 & 1)*8 + lr;
        int col = kc*16 + (t4 >> 1)*8;
        ldsm_x4(qh[kc], smB + (unsigned)((row*40 + col)*2));
        ldsm_x4(ql[kc], smB + (unsigned)((5120 + row*40 + col)*2));
    }
    __syncthreads();

    const int ldr = tid >> 2, ldc = (tid & 3)*8;
    auto loadkv = [&](int s, int j0){
        int gj = j0 + ldr;
        bool ok = gj < NTOK;
        size_t so = (size_t)(ok ? gj : 0)*D + ldc;
        unsigned doff = (unsigned)(s*5120 + (ldr*40 + ldc)*2);
        cp16(smB + doff,         kH + so, ok);
        cp16(smB + 10240 + doff, kL + so, ok);
        cp16(smB + 20480 + doff, vH + so, ok);
        cp16(smB + 30720 + doff, vL + so, ok);
        cpcommit();
    };

    float o[4][4];
    #pragma unroll
    for (int j = 0; j < 4; j++)
        #pragma unroll
        for (int q = 0; q < 4; q++) o[j][q] = 0.f;
    float m0 = -1e30f, m1 = -1e30f, l0 = 0.f, l1 = 0.f;
    const float scale = 0.17677669529663688f;

    loadkv(0, 0);
    int buf = 0;
    const int NJT = 14;
    for (int jt = 0; jt < NJT; jt++){
        const int j0 = jt*64;
        if (jt + 1 < NJT){ loadkv(buf ^ 1, (jt+1)*64); cpwait<1>(); }
        else cpwait<0>();
        __syncthreads();

        float s[8][4];
        #pragma unroll
        for (int nt = 0; nt < 8; nt++)
            #pragma unroll
            for (int q = 0; q < 4; q++) s[nt][q] = 0.f;

        #pragma unroll
        for (int kc = 0; kc < 2; kc++){
            #pragma unroll
            for (int pr = 0; pr < 4; pr++){
                int brow = pr*16 + (t4 >> 1)*8 + lr;
                int col  = kc*16 + (t4 & 1)*8;
                unsigned off = (unsigned)(buf*5120 + (brow*40 + col)*2);
                unsigned th[4], tl[4];
                ldsm_x4(th, smB + off);
                ldsm_x4(tl, smB + 10240 + off);
                unsigned bh0[2] = {th[0], th[1]}, bh1[2] = {th[2], th[3]};
                unsigned bl0[2] = {tl[0], tl[1]}, bl1[2] = {tl[2], tl[3]};
                mma_bf16(s[2*pr],   qh[kc], bh0);
                mma_bf16(s[2*pr],   qh[kc], bl0);
                mma_bf16(s[2*pr],   ql[kc], bh0);
                mma_bf16(s[2*pr+1], qh[kc], bh1);
                mma_bf16(s[2*pr+1], qh[kc], bl1);
                mma_bf16(s[2*pr+1], ql[kc], bh1);
            }
        }

        #pragma unroll
        for (int nt = 0; nt < 8; nt++)
            #pragma unroll
            for (int q = 0; q < 4; q++) s[nt][q] *= scale;
        if (j0 + 64 > NTOK){
            #pragma unroll
            for (int nt = 0; nt < 8; nt++){
                int c0 = j0 + nt*8 + (lane & 3)*2;
                if (c0     >= NTOK){ s[nt][0] = -1e30f; s[nt][2] = -1e30f; }
                if (c0 + 1 >= NTOK){ s[nt][1] = -1e30f; s[nt][3] = -1e30f; }
            }
        }

        float rm0 = -1e30f, rm1 = -1e30f;
        #pragma unroll
        for (int nt = 0; nt < 8; nt++){
            rm0 = fmaxf(rm0, fmaxf(s[nt][0], s[nt][1]));
            rm1 = fmaxf(rm1, fmaxf(s[nt][2], s[nt][3]));
        }
        rm0 = fmaxf(rm0, __shfl_xor_sync(0xffffffffu, rm0, 1));
        rm0 = fmaxf(rm0, __shfl_xor_sync(0xffffffffu, rm0, 2));
        rm1 = fmaxf(rm1, __shfl_xor_sync(0xffffffffu, rm1, 1));
        rm1 = fmaxf(rm1, __shfl_xor_sync(0xffffffffu, rm1, 2));
        float nm0 = fmaxf(m0, rm0), nm1 = fmaxf(m1, rm1);
        float a0 = __expf(m0 - nm0), a1 = __expf(m1 - nm1);
        float ps0 = 0.f, ps1 = 0.f;
        #pragma unroll
        for (int nt = 0; nt < 8; nt++){
            s[nt][0] = __expf(s[nt][0] - nm0);
            s[nt][1] = __expf(s[nt][1] - nm0);
            s[nt][2] = __expf(s[nt][2] - nm1);
            s[nt][3] = __expf(s[nt][3] - nm1);
            ps0 += s[nt][0] + s[nt][1];
            ps1 += s[nt][2] + s[nt][3];
        }
        ps0 += __shfl_xor_sync(0xffffffffu, ps0, 1);
        ps0 += __shfl_xor_sync(0xffffffffu, ps0, 2);
        ps1 += __shfl_xor_sync(0xffffffffu, ps1, 1);
        ps1 += __shfl_xor_sync(0xffffffffu, ps1, 2);
        l0 = l0*a0 + ps0; l1 = l1*a1 + ps1;
        m0 = nm0; m1 = nm1;
        #pragma unroll
        for (int nt = 0; nt < 4; nt++){
            o[nt][0] *= a0; o[nt][1] *= a0;
            o[nt][2] *= a1; o[nt][3] *= a1;
        }

        #pragma unroll
        for (int kc2 = 0; kc2 < 4; kc2++){
            unsigned pah[4], pal[4];
            {
                const float* u = s[2*kc2];
                const float* v2 = s[2*kc2 + 1];
                bf16 h0,lo0,h1,lo1;
                splitv(u[0], h0, lo0); splitv(u[1], h1, lo1);
                pah[0] = pack2u(h0, h1);   pal[0] = pack2u(lo0, lo1);
                splitv(u[2], h0, lo0); splitv(u[3], h1, lo1);
                pah[1] = pack2u(h0, h1);   pal[1] = pack2u(lo0, lo1);
                splitv(v2[0], h0, lo0); splitv(v2[1], h1, lo1);
                pah[2] = pack2u(h0, h1);   pal[2] = pack2u(lo0, lo1);
                splitv(v2[2], h0, lo0); splitv(v2[3], h1, lo1);
                pah[3] = pack2u(h0, h1);   pal[3] = pack2u(lo0, lo1);
            }
            #pragma unroll
            for (int pr2 = 0; pr2 < 2; pr2++){
                int krow = kc2*16 + (t4 & 1)*8 + lr;
                int ncol = pr2*16 + (t4 >> 1)*8;
                unsigned off = (unsigned)(buf*5120 + (krow*40 + ncol)*2);
                unsigned th[4], tl[4];
                ldsm_x4t(th, smB + 20480 + off);
                ldsm_x4t(tl, smB + 30720 + off);
                unsigned bh0[2] = {th[0], th[1]}, bh1[2] = {th[2], th[3]};
                unsigned bl0[2] = {tl[0], tl[1]}, bl1[2] = {tl[2], tl[3]};
                mma_bf16(o[2*pr2],   pah, bh0);
                mma_bf16(o[2*pr2],   pah, bl0);
                mma_bf16(o[2*pr2],   pal, bh0);
                mma_bf16(o[2*pr2+1], pah, bh1);
                mma_bf16(o[2*pr2+1], pah, bl1);
                mma_bf16(o[2*pr2+1], pal, bh1);
            }
        }
        __syncthreads();
        buf ^= 1;
    }

    float inv0 = 1.f / l0, inv1 = 1.f / l1;
    #pragma unroll
    for (int nt = 0; nt < 4; nt++){
        int row0 = i0 + w*16 + (lane >> 2);
        int col  = nt*8 + (lane & 3)*2;
        if (row0 < NTOK){
            size_t dst = ((size_t)b*NTOK + row0)*D + h*EH + col;
            bf16 h0,lo0,h1,lo1;
            splitv(o[nt][0]*inv0, h0, lo0); splitv(o[nt][1]*inv0, h1, lo1);
            *(__nv_bfloat162*)(p_att + dst)      = __halves2bfloat162(h0, h1);
            *(__nv_bfloat162*)(p_att + MD + dst) = __halves2bfloat162(lo0, lo1);
        }
        if (row0 + 8 < NTOK){
            size_t dst = ((size_t)b*NTOK + row0 + 8)*D + h*EH + col;
            bf16 h2,lo2,h3,lo3;
            splitv(o[nt][2]*inv1, h2, lo2); splitv(o[nt][3]*inv1, h3, lo3);
            *(__nv_bfloat162*)(p_att + dst)      = __halves2bfloat162(h2, h3);
            *(__nv_bfloat162*)(p_att + MD + dst) = __halves2bfloat162(lo2, lo3);
        }
    }
}

// ---------------- LayerNorm(x [- sub]) over D=256 (+ optional planes) ----
__global__ __launch_bounds__(256) void ln_kernel(const float* __restrict__ X,
                                                 const float* __restrict__ Sub,
                                                 const float* __restrict__ g,
                                                 const float* __restrict__ beta,
                                                 float* __restrict__ Out,
                                                 bf16* __restrict__ pH,
                                                 bf16* __restrict__ pL){
    int row = blockIdx.x, d = threadIdx.x;
    size_t i = (size_t)row*D + d;
    float v = X[i] - (Sub ? Sub[i] : 0.f);
    float mean = blockReduce(v, false) * (1.f/D);
    float dv = v - mean;
    float var = blockReduce(dv*dv, false) * (1.f/D);
    float o = dv * rsqrtf(var + EPS) * g[d] + beta[d];
    Out[i] = o;
    if (pH){
        bf16 hh, ll; splitv(o, hh, ll);
        pH[i] = hh; pL[i] = ll;
    }
}

// ---------------- final: transpose + de-standardize + 2-scale mean --------
__global__ __launch_bounds__(256) void final_kernel(float* __restrict__ out, int t){
    __shared__ float tile[32][33];
    int b = blockIdx.z;
    int p0 = blockIdx.x*32, n0 = blockIdx.y*32;
    int tx = threadIdx.x & 31, ty = threadIdx.x >> 5;
    #pragma unroll
    for (int i = 0; i < 4; i++){
        int n = n0 + ty + i*8, pp = p0 + tx;
        if (n < ENC && pp < DB)
            tile[ty + i*8][tx] = g_out[((size_t)b*NTOK + n)*DB + pp];
    }
    __syncthreads();
    #pragma unroll
    for (int i = 0; i < 4; i++){
        int pp = p0 + ty + i*8, n = n0 + tx;
        if (pp < DB && n < ENC){
            float v = tile[tx][ty + i*8]*g_std[b*ENC + n] + g_mean[b*ENC + n];
            v *= 0.5f;
            size_t idx = ((size_t)b*DB + pp)*ENC + n;
            if (t == 0) out[idx] = v; else out[idx] += v;
        }
    }
}

// ---------------- host ----------------
static inline int gsz(int nt){ return nt < 296 ? nt : 296; }
static void* sym(const void* s){ void* p; cudaGetSymbolAddress(&p, s); return p; }

extern "C" void kernel_launch(void* const* d_in, const int* in_sizes, int n_in,
                              void* d_out, int out_size){
    const float* mbx  = (const float*)d_in[0];
    const float* mbxm = (const float*)d_in[1];
    const float* embW = (const float*)d_in[4];
    const float* embB = (const float*)d_in[5];
    const float* Wq = (const float*)d_in[6];
    const float* Wk = (const float*)d_in[7];
    const float* Wv = (const float*)d_in[8];
    const float* Wo = (const float*)d_in[9];
    const float* W3 = (const float*)d_in[10];
    const float* W4 = (const float*)d_in[11];
    const float* bq = (const float*)d_in[12];
    const float* bk = (const float*)d_in[13];
    const float* bv = (const float*)d_in[14];
    const float* bo = (const float*)d_in[15];
    const float* b3 = (const float*)d_in[16];
    const float* b4 = (const float*)d_in[17];
    const float* W1 = (const float*)d_in[18];
    const float* b1 = (const float*)d_in[19];
    const float* W2 = (const float*)d_in[20];
    const float* b2 = (const float*)d_in[21];
    const float* W5 = (const float*)d_in[22];
    const float* b5 = (const float*)d_in[23];
    const float* W6 = (const float*)d_in[24];
    const float* b6 = (const float*)d_in[25];
    const float* ln1g = (const float*)d_in[26];
    const float* ln1b = (const float*)d_in[27];
    const float* ln2g = (const float*)d_in[28];
    const float* ln2b = (const float*)d_in[29];
    float* out = (float*)d_out;

    float* hF   = (float*)sym(g_h);
    float* xatt = (float*)sym(g_xatt);
    float* xln  = (float*)sym(g_xln);
    float* hhF  = (float*)sym(g_hh);
    float* outF = (float*)sym(g_out);

    bf16* xinP = (bf16*)sym(p_xin);
    bf16* hP   = (bf16*)sym(p_h);
    bf16* qkvP = (bf16*)sym(p_qkv);
    bf16* attP = (bf16*)sym(p_att);
    bf16* xlnP = (bf16*)sym(p_xln);
    bf16* y1P  = (bf16*)sym(p_y1);
    bf16* xsP  = (bf16*)sym(p_xs);
    bf16* xattP = (bf16*)sym(p_xatt);
    bf16* yP   = (bf16*)sym(p_y);
    bf16* embWP = (bf16*)sym(p_embW);
    bf16* WqP = (bf16*)sym(p_Wq); bf16* WkP = (bf16*)sym(p_Wk);
    bf16* WvP = (bf16*)sym(p_Wv); bf16* WoP = (bf16*)sym(p_Wo);
    bf16* W3P = (bf16*)sym(p_W3); bf16* W4P = (bf16*)sym(p_W4);
    bf16* W1P = (bf16*)sym(p_W1); bf16* W2P = (bf16*)sym(p_W2);
    bf16* W5P = (bf16*)sym(p_W5); bf16* W6P = (bf16*)sym(p_W6);

    const size_t XN  = (size_t)MROWS*SEQP;
    const size_t EWN = (size_t)256*SEQP;
    const size_t WDD = (size_t)LAYERS*D*D;
    const size_t W1N = (size_t)LAYERS*DFF*D;
    const size_t W5N = (size_t)LAYERS*DB*2*D;
    const size_t Y1N = (size_t)MROWS*DFF;

    cudaFuncSetAttribute(mma_gemm<0>, cudaFuncAttributeMaxDynamicSharedMemorySize, 61440);
    cudaFuncSetAttribute(mma_gemm<1>, cudaFuncAttributeMaxDynamicSharedMemorySize, 61440);
    cudaFuncSetAttribute(mma_gemm<2>, cudaFuncAttributeMaxDynamicSharedMemorySize, 61440);
    cudaFuncSetAttribute(mma_gemm2<0>, cudaFuncAttributeMaxDynamicSharedMemorySize, 61440);
    cudaFuncSetAttribute(mma_gemm2<1>, cudaFuncAttributeMaxDynamicSharedMemorySize, 61440);

    // weight splits (one batched launch + embed pad)
    {
        WSArgs ws;
        const float* ss[10] = {Wq, Wk, Wv, Wo, W3, W4, W1, W2, W5, W6};
        bf16* hh[10] = {WqP, WkP, WvP, WoP, W3P, W4P, W1P, W2P, W5P, W6P};
        size_t nn[10] = {WDD, WDD, WDD, WDD, WDD, WDD, W1N, W1N, W5N, W5N};
        for (int i = 0; i < 10; i++){
            ws.s[i] = ss[i]; ws.h[i] = hh[i]; ws.l[i] = hh[i] + nn[i]; ws.n[i] = (int)nn[i];
        }
        wsplit_all<<<dim3(288, 10), 256>>>(ws);
        wsplit_pad<<<(unsigned)((EWN + 255)/256), 256>>>(embW, embWP, embWP + EWN, 256, SEQ, SEQP);
    }

    const int tm = 55;    // ceil(6928/128)
    const int tm64 = 109; // ceil(6928/64)

    for (int t = 0; t < TS; t++){
        stats_kernel<<<dim3((ENC + 255)/256, B_), 256>>>(mbx, t);
        xin_kernel<<<(unsigned)((XN + 255)/256), 256>>>(mbx, mbxm, t);

        {   // embed -> fp32 h + planes
            GemmArgs a = {};
            a.aH[0] = xinP; a.aL[0] = xinP + XN;
            a.wH[0] = embWP; a.wL[0] = embWP + EWN;
            a.bias[0] = embB; a.C[0] = hF;
            a.cH[0] = hP; a.cL[0] = hP + MD;
            mma_gemm<0><<<gsz(tm*4), 256, 61440>>>(a, MROWS, D, SEQP, 4, tm*4, tm*4);
        }

        for (int l = 0; l < LAYERS; l++){
            {   // QKV -> planes
                GemmArgs a = {};
                for (int z = 0; z < 3; z++){
                    a.aH[z] = hP; a.aL[z] = hP + MD;
                    a.cH[z] = qkvP + (size_t)z*MD;
                    a.cL[z] = qkvP + 3*MD + (size_t)z*MD;
                }
                a.wH[0] = WqP + (size_t)l*D*D; a.wL[0] = WqP + WDD + (size_t)l*D*D;
                a.wH[1] = WkP + (size_t)l*D*D; a.wL[1] = WkP + WDD + (size_t)l*D*D;
                a.wH[2] = WvP + (size_t)l*D*D; a.wL[2] = WvP + WDD + (size_t)l*D*D;
                a.bias[0] = bq + l*D; a.bias[1] = bk + l*D; a.bias[2] = bv + l*D;
                mma_gemm<0><<<gsz(tm*4*3), 256, 61440>>>(a, MROWS, D, D, 4, tm*4, tm*4*3);
            }

            flash_attn<<<dim3(7, B_*NH), 256>>>();

            {   // Wo -> fp32 xatt + planes
                GemmArgs a = {};
                a.aH[0] = attP; a.aL[0] = attP + MD;
                a.wH[0] = WoP + (size_t)l*D*D; a.wL[0] = WoP + WDD + (size_t)l*D*D;
                a.bias[0] = bo + l*D; a.C[0] = xatt;
                a.cH[0] = xattP; a.cL[0] = xattP + MD;
                mma_gemm<0><<<gsz(tm*4), 256, 61440>>>(a, MROWS, D, D, 4, tm*4, tm*4);
            }

            ln_kernel<<<MROWS, 256>>>(hF, xatt, ln1g + l*D, ln1b + l*D, xln,
                                      xlnP, xlnP + MD);

            {   // W1 + GELU -> y1 planes
                GemmArgs a = {};
                a.aH[0] = xlnP; a.aL[0] = xlnP + MD;
                a.wH[0] = W1P + (size_t)l*DFF*D; a.wL[0] = W1P + W1N + (size_t)l*DFF*D;
                a.bias[0] = b1 + l*DFF;
                a.cH[0] = y1P; a.cL[0] = y1P + Y1N;
                mma_gemm<1><<<gsz(tm*8), 256, 61440>>>(a, MROWS, DFF, D, 8, tm*8, tm*8);
            }
            {   // W2 -> y planes + xs=(xln-y) planes (sub fused)
                GemmArgs a = {};
                a.aH[0] = y1P; a.aL[0] = y1P + Y1N;
                a.wH[0] = W2P + (size_t)l*D*DFF; a.wL[0] = W2P + W1N + (size_t)l*D*DFF;
                a.bias[0] = b2 + l*D;
                a.cH[0] = yP; a.cL[0] = yP + MD;
                a.xsub[0] = xln;
                a.c2H[0] = xsP; a.c2L[0] = xsP + MD;
                mma_gemm<2><<<gsz(tm*4), 256, 61440>>>(a, MROWS, D, DFF, 4, tm*4, tm*4);
            }

            {   // fused W3/W4 -> hh = sigmoid(.)*(.)
                Gemm2Args a = {};
                a.a0H = xsP; a.a0L = xsP + MD; a.a1H = xsP; a.a1L = xsP + MD;
                a.kSplit = 1 << 30; a.aStride = D;
                a.w1H = W3P + (size_t)l*D*D; a.w1L = W3P + WDD + (size_t)l*D*D;
                a.w2H = W4P + (size_t)l*D*D; a.w2L = W4P + WDD + (size_t)l*D*D;
                a.b1 = b3 + l*D; a.b2 = b4 + l*D;
                a.Cout = hhF; a.sub = 0;
                mma_gemm2<0><<<gsz(tm64*4), 256, 61440>>>(a, MROWS, D, D, 4, tm64*4);
            }

            {   // fused W5/W6 over cat(xatt,y) -> g_out (with layer subtract)
                Gemm2Args a = {};
                a.a0H = xattP; a.a0L = xattP + MD;
                a.a1H = yP;    a.a1L = yP + MD;
                a.kSplit = D; a.aStride = D;
                a.w1H = W5P + (size_t)l*DB*2*D; a.w1L = W5P + W5N + (size_t)l*DB*2*D;
                a.w2H = W6P + (size_t)l*DB*2*D; a.w2L = W6P + W5N + (size_t)l*DB*2*D;
                a.b1 = b5 + l*DB; a.b2 = b6 + l*DB;
                a.Cout = outF; a.sub = l;
                mma_gemm2<1><<<gsz(tm64*12), 256, 61440>>>(a, MROWS, DB, 2*D, 12, tm64*12);
            }

            ln_kernel<<<MROWS, 256>>>(hhF, (const float*)nullptr,
                                      ln2g + l*D, ln2b + l*D, hF, hP, hP + MD);
        }

        final_kernel<<<dim3((DB + 31)/32, (ENC + 31)/32, B_), 256>>>(out, t);
    }
}